// round 10
// baseline (speedup 1.0000x reference)
#include <cuda_runtime.h>
#include <cuda_bf16.h>
#include <cstdint>
#include <math.h>

typedef unsigned int u32;

#define NVV 50000
#define NCC 210000
#define NEE 630000
#define NGG 32
#define RNDS 16
#define EPSV 1e-6f
#define VMB 12500
#define GCB 1641

// ---------------- scratch (static device globals; no allocation) ----------------
__device__ float g_variables[NVV * 64];
__device__ float g_clauses[NCC * 64];
__device__ float g_unit[NVV * 256];      // [vgrad | variables | vl_pos | vl_neg]
__device__ float g_cdata[NCC * 128];     // clause_data = [varloss_all | prenorm]
__device__ float g_cl[NCC * 64];         // 4*exp(-cv) per clause (for vmsg)
__device__ float g_ch[NCC * 64];         // o-MLP hidden
__device__ float g_query[NVV * 64];
__device__ float g_uout[NVV * 64];

__device__ int   g_cnt[2 * NVV];
__device__ int   g_off[2 * NVV + 1];
__device__ int   g_cur[2 * NVV];
__device__ int   g_ecl[NEE];
__device__ float g_dw[2 * NVV];
__device__ float g_vdw[NVV];
__device__ int   g_gcnt_v[NGG];
__device__ int   g_gcnt_c[NGG];
__device__ int   g_goff_v[NGG + 1];
__device__ int   g_goff_c[NGG + 1];
__device__ float g_mean[NGG * 64];
__device__ float g_rstd[NGG * 64];
__device__ float g_bsum[GCB * 256];      // per-block moments: s1A|s2A|s1B|s2B (64 each)
__device__ int   g_bgid[GCB * 2];        // per-block group ids A/B

// bf16 hi/lo weight pools (padded K)
#define OQ0 0
#define OQ1 6144
#define OC0 10240
#define OC1 26624
#define OU0 43008
#define OU1 75776
#define OU2 92160
#define OO0 100352
#define WPOOL 104448
__device__ __nv_bfloat16 g_whi[WPOOL];
__device__ __nv_bfloat16 g_wlo[WPOOL];

#define SMEMSZ 110592

static inline int cdiv(int a, int b) { return (a + b - 1) / b; }

// ---------------- setup kernels (3 launches; #4 = q-MLP for profiling) -------
__global__ void k_setup_init(const float* __restrict__ qW0, const float* __restrict__ qW1,
                             const float* __restrict__ cW0, const float* __restrict__ cW1,
                             const float* __restrict__ uW0, const float* __restrict__ uW1,
                             const float* __restrict__ uW2, const float* __restrict__ oW0) {
    int i = blockIdx.x * 256 + threadIdx.x;
    if (i < NCC * 64) g_clauses[i] = 1.f;
    if (i < NVV * 64) {
        g_variables[i] = 1.f;
        int r = i >> 6;
        int c = i & 63;
        g_unit[r * 256 + 64 + c] = 1.f;
    }
    if (i < 2 * NVV) g_cnt[i] = 0;
    if (i < NGG) {
        g_gcnt_v[i] = 0;
        g_gcnt_c[i] = 0;
    }
    if (i < WPOOL) {
        const float* W;
        int K, N, local;
        if (i < OQ1)      { W = qW0; K = 68;  N = 64;  local = i - OQ0; }
        else if (i < OC0) { W = qW1; K = 64;  N = 64;  local = i - OQ1; }
        else if (i < OC1) { W = cW0; K = 128; N = 128; local = i - OC0; }
        else if (i < OU0) { W = cW1; K = 128; N = 128; local = i - OC1; }
        else if (i < OU1) { W = uW0; K = 256; N = 128; local = i - OU0; }
        else if (i < OU2) { W = uW1; K = 128; N = 128; local = i - OU1; }
        else if (i < OO0) { W = uW2; K = 128; N = 64;  local = i - OU2; }
        else              { W = oW0; K = 64;  N = 64;  local = i - OO0; }
        int k = local / N;
        float v = (k < K) ? W[local] : 0.f;
        __nv_bfloat16 h = __float2bfloat16(v);
        g_whi[i] = h;
        g_wlo[i] = __float2bfloat16(v - __bfloat162float(h));
    }
}

__global__ void k_countall(const int* __restrict__ lit_idx,
                           const int* __restrict__ var_gid,
                           const int* __restrict__ clause_gid) {
    int i = blockIdx.x * 256 + threadIdx.x;
    if (i < NEE) atomicAdd(&g_cnt[lit_idx[i]], 1);
    if (i < NVV) atomicAdd(&g_gcnt_v[var_gid[i]], 1);
    if (i < NCC) atomicAdd(&g_gcnt_c[clause_gid[i]], 1);
}

__global__ void k_scan() {
    __shared__ int ssum[1024];
    int tid = threadIdx.x;
    const int Ntot = 2 * NVV;
    int chunk = (Ntot + 1023) / 1024;
    int base = tid * chunk;
    int s = 0;
    for (int i = 0; i < chunk; i++) {
        int idx = base + i;
        if (idx < Ntot) s += g_cnt[idx];
    }
    ssum[tid] = s;
    __syncthreads();
    for (int d = 1; d < 1024; d <<= 1) {
        int v = (tid >= d) ? ssum[tid - d] : 0;
        __syncthreads();
        ssum[tid] += v;
        __syncthreads();
    }
    int run = (tid == 0) ? 0 : ssum[tid - 1];
    for (int i = 0; i < chunk; i++) {
        int idx = base + i;
        if (idx < Ntot) {
            g_off[idx] = run;
            g_cur[idx] = run;
            int c = g_cnt[idx];
            g_dw[idx] = rsqrtf(fmaxf((float)c, 1.f));
            run += c;
        }
    }
    if (tid == 1023) g_off[Ntot] = ssum[1023];
    if (tid == 0) {
        int a = 0;
        for (int g = 0; g < NGG; g++) {
            g_goff_v[g] = a;
            a += g_gcnt_v[g];
        }
        g_goff_v[NGG] = a;
        int b = 0;
        for (int g = 0; g < NGG; g++) {
            g_goff_c[g] = b;
            b += g_gcnt_c[g];
        }
        g_goff_c[NGG] = b;
    }
    __syncthreads();
    for (int v = tid; v < NVV; v += 1024)
        g_vdw[v] = 4.f * rsqrtf(fmaxf((float)(g_cnt[v] + g_cnt[NVV + v]), 1.f));
}

__global__ void k_fill(const int* __restrict__ lit_idx) {
    int e = blockIdx.x * 256 + threadIdx.x;
    if (e < NEE) {
        int p = atomicAdd(&g_cur[lit_idx[e]], 1);
        g_ecl[p] = e / 3;   // clause_idx = repeat(arange(NC), 3)
    }
}

// ---------------- MMA helpers ----------------
__device__ __forceinline__ u32 smem_u32(const void* p) {
    return (u32)__cvta_generic_to_shared(p);
}

__device__ __forceinline__ void ldsm4(u32& r0, u32& r1, u32& r2, u32& r3, u32 a) {
    asm volatile("ldmatrix.sync.aligned.m8n8.x4.shared.b16 {%0,%1,%2,%3}, [%4];"
                 : "=r"(r0), "=r"(r1), "=r"(r2), "=r"(r3) : "r"(a));
}

__device__ __forceinline__ void ldsm4t(u32& r0, u32& r1, u32& r2, u32& r3, u32 a) {
    asm volatile("ldmatrix.sync.aligned.m8n8.x4.trans.shared.b16 {%0,%1,%2,%3}, [%4];"
                 : "=r"(r0), "=r"(r1), "=r"(r2), "=r"(r3) : "r"(a));
}

__device__ __forceinline__ void mma_bf16(float* c, const u32* a, const u32* b) {
    asm volatile(
        "mma.sync.aligned.m16n8k16.row.col.f32.bf16.bf16.f32 "
        "{%0,%1,%2,%3}, {%4,%5,%6,%7}, {%8,%9}, {%0,%1,%2,%3};"
        : "+f"(c[0]), "+f"(c[1]), "+f"(c[2]), "+f"(c[3])
        : "r"(a[0]), "r"(a[1]), "r"(a[2]), "r"(a[3]), "r"(b[0]), "r"(b[1]));
}

__device__ __forceinline__ float softplusf(float x) {
    return fmaxf(x, 0.f) + log1pf(expf(-fabsf(x)));
}

__device__ __forceinline__ void bsplit(float v, __nv_bfloat16& h, __nv_bfloat16& l) {
    h = __float2bfloat16(v);
    l = __float2bfloat16(v - __bfloat162float(h));
}

// W slab load: 32 rows x NW cols of hi/lo into regs
template <int NW>
__device__ __forceinline__ void wload(int s, int tid,
                                      const __nv_bfloat16* __restrict__ Wh,
                                      const __nv_bfloat16* __restrict__ Wl,
                                      uint4* th, uint4* tl) {
    const uint4* wh4 = reinterpret_cast<const uint4*>(Wh + (size_t)s * 32 * NW);
    const uint4* wl4 = reinterpret_cast<const uint4*>(Wl + (size_t)s * 32 * NW);
    const int NW4 = NW / 64;
    for (int i = 0; i < NW4; i++) {
        th[i] = wh4[tid + i * 256];
        tl[i] = wl4[tid + i * 256];
    }
}

// GEMM phase reading A from smem (Hh/Hl), W streamed global->smem with reg prefetch
template <int NW, int MT>
__device__ __forceinline__ void mlp_phase(const __nv_bfloat16* Hh, const __nv_bfloat16* Hl,
                                          int hstr, int Kdim,
                                          const __nv_bfloat16* __restrict__ Wh,
                                          const __nv_bfloat16* __restrict__ Wl,
                                          __nv_bfloat16* sWh, __nv_bfloat16* sWl,
                                          int tid, float acc[][4][4]) {
    const int lane = tid & 31;
    const int warp = tid >> 5;
    int wm, wn;
    if (NW == 128) { wm = warp & 1; wn = warp >> 1; }
    else           { wm = warp & 3; wn = warp >> 2; }
    const int wrow = wm * 16 * MT;
    const int wcol = wn * 32;
    const int BSTR = NW + 8;
    const int NW4 = NW / 64;

#pragma unroll
    for (int i = 0; i < MT; i++)
#pragma unroll
        for (int j = 0; j < 4; j++)
#pragma unroll
            for (int q = 0; q < 4; q++) acc[i][j][q] = 0.f;

    uint4 th[2], tl[2];
    wload<NW>(0, tid, Wh, Wl, th, tl);
    const int S = Kdim / 32;
    for (int s = 0; s < S; s++) {
#pragma unroll
        for (int i = 0; i < NW4; i++) {
            int f = tid + i * 256;
            int r = f / (NW / 8);
            int n8 = f % (NW / 8);
            *reinterpret_cast<uint4*>(&sWh[r * BSTR + n8 * 8]) = th[i];
            *reinterpret_cast<uint4*>(&sWl[r * BSTR + n8 * 8]) = tl[i];
        }
        __syncthreads();
        if (s + 1 < S) wload<NW>(s + 1, tid, Wh, Wl, th, tl);
#pragma unroll
        for (int ks = 0; ks < 32; ks += 16) {
            int kk = s * 32 + ks;
            u32 ah[MT][4], al[MT][4];
#pragma unroll
            for (int mt = 0; mt < MT; mt++) {
                int r = wrow + mt * 16 + (lane & 15);
                int ko = kk + ((lane >> 4) << 3);
                ldsm4(ah[mt][0], ah[mt][1], ah[mt][2], ah[mt][3],
                      smem_u32(&Hh[r * hstr + ko]));
                ldsm4(al[mt][0], al[mt][1], al[mt][2], al[mt][3],
                      smem_u32(&Hl[r * hstr + ko]));
            }
            u32 bh[4][2], bl[4][2];
#pragma unroll
            for (int half = 0; half < 2; half++) {
                int k = ks + (lane & 15);
                int n = wcol + half * 16 + ((lane >> 4) << 3);
                u32 r0, r1, r2, r3;
                ldsm4t(r0, r1, r2, r3, smem_u32(&sWh[k * BSTR + n]));
                bh[half * 2 + 0][0] = r0;
                bh[half * 2 + 0][1] = r1;
                bh[half * 2 + 1][0] = r2;
                bh[half * 2 + 1][1] = r3;
                ldsm4t(r0, r1, r2, r3, smem_u32(&sWl[k * BSTR + n]));
                bl[half * 2 + 0][0] = r0;
                bl[half * 2 + 0][1] = r1;
                bl[half * 2 + 1][0] = r2;
                bl[half * 2 + 1][1] = r3;
            }
#pragma unroll
            for (int mt = 0; mt < MT; mt++)
#pragma unroll
                for (int nt = 0; nt < 4; nt++) mma_bf16(acc[mt][nt], ah[mt], bh[nt]);
#pragma unroll
            for (int mt = 0; mt < MT; mt++)
#pragma unroll
                for (int nt = 0; nt < 4; nt++) mma_bf16(acc[mt][nt], ah[mt], bl[nt]);
#pragma unroll
            for (int mt = 0; mt < MT; mt++)
#pragma unroll
                for (int nt = 0; nt < 4; nt++) mma_bf16(acc[mt][nt], al[mt], bh[nt]);
        }
        __syncthreads();
    }
}

// epilogue: acc -> smem hidden (bias + leaky, hi/lo bf16)
template <int NW, int MT>
__device__ __forceinline__ void epi_to_smem(float acc[][4][4],
                                            const float* __restrict__ bias,
                                            __nv_bfloat16* Hh, __nv_bfloat16* Hl,
                                            int hstr, int tid) {
    const int lane = tid & 31;
    const int warp = tid >> 5;
    int wm, wn;
    if (NW == 128) { wm = warp & 1; wn = warp >> 1; }
    else           { wm = warp & 3; wn = warp >> 2; }
    const int wrow = wm * 16 * MT;
    const int wcol = wn * 32;
#pragma unroll
    for (int mt = 0; mt < MT; mt++) {
#pragma unroll
        for (int nt = 0; nt < 4; nt++) {
            int c = wcol + nt * 8 + (lane & 3) * 2;
            float b0 = bias[c];
            float b1 = bias[c + 1];
#pragma unroll
            for (int pr = 0; pr < 2; pr++) {
                int r = wrow + mt * 16 + (lane >> 2) + pr * 8;
                float v0 = acc[mt][nt][2 * pr + 0] + b0;
                float v1 = acc[mt][nt][2 * pr + 1] + b1;
                v0 = v0 > 0.f ? v0 : 0.2f * v0;
                v1 = v1 > 0.f ? v1 : 0.2f * v1;
                __nv_bfloat16 h0, l0, h1, l1;
                bsplit(v0, h0, l0);
                bsplit(v1, h1, l1);
                Hh[r * hstr + c] = h0;
                Hh[r * hstr + c + 1] = h1;
                Hl[r * hstr + c] = l0;
                Hl[r * hstr + c + 1] = l1;
            }
        }
    }
}

// epilogue: acc -> global out (bias only); optionally stage 64 stat cols to smem fp32
template <int NW, int MT>
__device__ __forceinline__ void epi_to_global(float acc[][4][4],
                                              const float* __restrict__ bias,
                                              float* __restrict__ OUT, int M,
                                              int row0, int tid,
                                              float* sOut, int c0) {
    const int lane = tid & 31;
    const int warp = tid >> 5;
    int wm, wn;
    if (NW == 128) { wm = warp & 1; wn = warp >> 1; }
    else           { wm = warp & 3; wn = warp >> 2; }
    const int wrow = wm * 16 * MT;
    const int wcol = wn * 32;
#pragma unroll
    for (int mt = 0; mt < MT; mt++) {
#pragma unroll
        for (int nt = 0; nt < 4; nt++) {
            int c = wcol + nt * 8 + (lane & 3) * 2;
            float b0 = bias[c];
            float b1 = bias[c + 1];
#pragma unroll
            for (int pr = 0; pr < 2; pr++) {
                int rl = wrow + mt * 16 + (lane >> 2) + pr * 8;
                int rr = row0 + rl;
                float v0 = acc[mt][nt][2 * pr + 0] + b0;
                float v1 = acc[mt][nt][2 * pr + 1] + b1;
                if (rr < M) {
                    *reinterpret_cast<float2*>(OUT + (size_t)rr * NW + c) =
                        make_float2(v0, v1);
                }
                if (sOut != 0 && c >= c0 && c < c0 + 64) {
                    sOut[rl * 64 + (c - c0)] = v0;
                    sOut[rl * 64 + (c - c0) + 1] = v1;
                }
            }
        }
    }
}

// ---------------- fused multi-layer MLP kernel ----------------
// MODE 0: A = A0[M, lda0]            (u-MLP, K1 = 32*K1S)
// MODE 1: A = [A0(64) | noise(4) | 0] (q-MLP, K1S = 3)
// MODE 2: A = [clauses(64) | 4*exp(-cv(query, lit))] (c-MLP, K1S = 4); WCL -> write g_cl
// gid != 0 => compute per-block group moments of output cols [statc0, statc0+64)
template <int K1S, int MODE, int H1, int NL, int H2, int HOUT, int WCL>
__launch_bounds__(256)
__global__ void k_mlp(int M,
                      const float* __restrict__ A0, int lda0,
                      const float* __restrict__ A1,
                      const int* __restrict__ lit,
                      const float* __restrict__ query,
                      float* __restrict__ clout,
                      const int* __restrict__ gid,
                      float* __restrict__ bsum,
                      int* __restrict__ bgid,
                      int statc0,
                      const __nv_bfloat16* __restrict__ W1h,
                      const __nv_bfloat16* __restrict__ W1l,
                      const float* __restrict__ b1,
                      const __nv_bfloat16* __restrict__ W2h,
                      const __nv_bfloat16* __restrict__ W2l,
                      const float* __restrict__ b2,
                      const __nv_bfloat16* __restrict__ W3h,
                      const __nv_bfloat16* __restrict__ W3l,
                      const float* __restrict__ b3,
                      float* __restrict__ OUT) {
    extern __shared__ char smem[];
    const int ASTR = 40;
    __nv_bfloat16* sAh = (__nv_bfloat16*)smem;            // 128*40
    __nv_bfloat16* sAl = sAh + 128 * ASTR;
    __nv_bfloat16* sWh = sAl + 128 * ASTR;                // 32*136
    __nv_bfloat16* sWl = sWh + 32 * 136;
    __nv_bfloat16* sHh = sWl + 32 * 136;                  // 128*136
    __nv_bfloat16* sHl = sHh + 128 * 136;
    int* sLit = (int*)(sHl + 128 * 136);                  // 128*3
    int* sGid = sLit + 384;                               // 128
    int* sMeta = sGid + 128;                              // 4

    const int tid = threadIdx.x;
    const int lane = tid & 31;
    const int warp = tid >> 5;
    const int row0 = blockIdx.x * 128;
    const int HSTR1 = H1 + 8;

    if (MODE == 2) {
        for (int i = tid; i < 128 * 3; i += 256) {
            int r = i / 3;
            int j = i % 3;
            int row = row0 + r;
            sLit[i] = (row < M) ? lit[row * 3 + j] : 0;
        }
    }
    if (gid != 0) {
        for (int i = tid; i < 128; i += 256) {
            int row = row0 + i;
            sGid[i] = (row < M) ? gid[row] : -1;
        }
    }
    __syncthreads();
    if (gid != 0 && tid == 0) {
        int gA = sGid[0];
        int gB = gA;
        for (int r = 1; r < 128; r++) {
            int gg = sGid[r];
            if (gg >= 0 && gg != gA) { gB = gg; break; }
        }
        sMeta[0] = gB;
    }

    // ---- phase 1: global A -> hidden1 ----
    const int MT1 = (H1 == 128) ? 4 : 2;
    int wm1, wn1;
    if (H1 == 128) { wm1 = warp & 1; wn1 = warp >> 1; }
    else           { wm1 = warp & 3; wn1 = warp >> 2; }
    const int wrow1 = wm1 * 16 * MT1;
    const int wcol1 = wn1 * 32;
    const int BSTR1 = H1 + 8;
    const int NW41 = H1 / 64;

    float acc[4][4][4];
#pragma unroll
    for (int i = 0; i < MT1; i++)
#pragma unroll
        for (int j = 0; j < 4; j++)
#pragma unroll
            for (int q = 0; q < 4; q++) acc[i][j][q] = 0.f;

    for (int s = 0; s < K1S; s++) {
        // A slab -> regs
        float4 ar[4];
#pragma unroll
        for (int i = 0; i < 4; i++) {
            int f = tid + i * 256;
            int r = f >> 3;
            int c4 = f & 7;
            int col = s * 32 + c4 * 4;
            int row = row0 + r;
            float4 v = make_float4(0.f, 0.f, 0.f, 0.f);
            if (row < M) {
                if (MODE == 0) {
                    v = *reinterpret_cast<const float4*>(A0 + (size_t)row * lda0 + col);
                } else if (MODE == 1) {
                    if (col < 64)
                        v = *reinterpret_cast<const float4*>(A0 + (size_t)row * 64 + col);
                    else if (col == 64)
                        v = *reinterpret_cast<const float4*>(A1 + (size_t)row * 4);
                } else {
                    if (s < 2) {
                        v = *reinterpret_cast<const float4*>(A0 + (size_t)row * 64 + col);
                    } else {
                        int fc = col - 64;
                        float cv0 = 0.f, cv1 = 0.f, cv2 = 0.f, cv3 = 0.f;
#pragma unroll
                        for (int j = 0; j < 3; j++) {
                            int l = sLit[r * 3 + j];
                            int qr = (l < NVV) ? l : (l - NVV);
                            float sg = (l < NVV) ? 1.f : -1.f;
                            float4 qv = *reinterpret_cast<const float4*>(
                                query + (size_t)qr * 64 + fc);
                            cv0 += softplusf(sg * qv.x);
                            cv1 += softplusf(sg * qv.y);
                            cv2 += softplusf(sg * qv.z);
                            cv3 += softplusf(sg * qv.w);
                        }
                        v = make_float4(4.f * expf(-cv0), 4.f * expf(-cv1),
                                        4.f * expf(-cv2), 4.f * expf(-cv3));
                        if (WCL)
                            *reinterpret_cast<float4*>(clout + (size_t)row * 64 + fc) = v;
                    }
                }
            }
            ar[i] = v;
        }
        // W slab -> regs
        uint4 th[2], tl[2];
        const uint4* wh4 = reinterpret_cast<const uint4*>(W1h + (size_t)s * 32 * H1);
        const uint4* wl4 = reinterpret_cast<const uint4*>(W1l + (size_t)s * 32 * H1);
#pragma unroll
        for (int i = 0; i < NW41; i++) {
            th[i] = wh4[tid + i * 256];
            tl[i] = wl4[tid + i * 256];
        }
        __syncthreads();
        // regs -> smem
#pragma unroll
        for (int i = 0; i < 4; i++) {
            int f = tid + i * 256;
            int r = f >> 3;
            int c4 = f & 7;
            float4 v = ar[i];
            __nv_bfloat16 h0, l0, h1, l1, h2, l2, h3, l3;
            bsplit(v.x, h0, l0);
            bsplit(v.y, h1, l1);
            bsplit(v.z, h2, l2);
            bsplit(v.w, h3, l3);
            __nv_bfloat16* ph = &sAh[r * ASTR + c4 * 4];
            __nv_bfloat16* pl = &sAl[r * ASTR + c4 * 4];
            ph[0] = h0; ph[1] = h1; ph[2] = h2; ph[3] = h3;
            pl[0] = l0; pl[1] = l1; pl[2] = l2; pl[3] = l3;
        }
#pragma unroll
        for (int i = 0; i < NW41; i++) {
            int f = tid + i * 256;
            int r = f / (H1 / 8);
            int n8 = f % (H1 / 8);
            *reinterpret_cast<uint4*>(&sWh[r * BSTR1 + n8 * 8]) = th[i];
            *reinterpret_cast<uint4*>(&sWl[r * BSTR1 + n8 * 8]) = tl[i];
        }
        __syncthreads();
        // MMA over this 32-slab
#pragma unroll
        for (int ks = 0; ks < 32; ks += 16) {
            u32 ah[4][4], al[4][4];
#pragma unroll
            for (int mt = 0; mt < MT1; mt++) {
                int r = wrow1 + mt * 16 + (lane & 15);
                int ko = ks + ((lane >> 4) << 3);
                ldsm4(ah[mt][0], ah[mt][1], ah[mt][2], ah[mt][3],
                      smem_u32(&sAh[r * ASTR + ko]));
                ldsm4(al[mt][0], al[mt][1], al[mt][2], al[mt][3],
                      smem_u32(&sAl[r * ASTR + ko]));
            }
            u32 bh[4][2], bl[4][2];
#pragma unroll
            for (int half = 0; half < 2; half++) {
                int k = ks + (lane & 15);
                int n = wcol1 + half * 16 + ((lane >> 4) << 3);
                u32 r0, r1, r2, r3;
                ldsm4t(r0, r1, r2, r3, smem_u32(&sWh[k * BSTR1 + n]));
                bh[half * 2 + 0][0] = r0;
                bh[half * 2 + 0][1] = r1;
                bh[half * 2 + 1][0] = r2;
                bh[half * 2 + 1][1] = r3;
                ldsm4t(r0, r1, r2, r3, smem_u32(&sWl[k * BSTR1 + n]));
                bl[half * 2 + 0][0] = r0;
                bl[half * 2 + 0][1] = r1;
                bl[half * 2 + 1][0] = r2;
                bl[half * 2 + 1][1] = r3;
            }
#pragma unroll
            for (int mt = 0; mt < MT1; mt++)
#pragma unroll
                for (int nt = 0; nt < 4; nt++) mma_bf16(acc[mt][nt], ah[mt], bh[nt]);
#pragma unroll
            for (int mt = 0; mt < MT1; mt++)
#pragma unroll
                for (int nt = 0; nt < 4; nt++) mma_bf16(acc[mt][nt], ah[mt], bl[nt]);
#pragma unroll
            for (int mt = 0; mt < MT1; mt++)
#pragma unroll
                for (int nt = 0; nt < 4; nt++) mma_bf16(acc[mt][nt], al[mt], bh[nt]);
        }
        __syncthreads();
    }
    // hidden1 -> smem (leaky + bias)
    epi_to_smem<H1, (H1 == 128) ? 4 : 2>(acc, b1, sHh, sHl, HSTR1, tid);
    __syncthreads();

    float* sOut = (gid != 0) ? (float*)sHh : (float*)0;

    if (NL == 2) {
        mlp_phase<HOUT, (HOUT == 128) ? 4 : 2>(sHh, sHl, HSTR1, H1, W2h, W2l,
                                               sWh, sWl, tid, acc);
        epi_to_global<HOUT, (HOUT == 128) ? 4 : 2>(acc, b2, OUT, M, row0, tid,
                                                   sOut, statc0);
    } else {
        mlp_phase<H2, (H2 == 128) ? 4 : 2>(sHh, sHl, HSTR1, H1, W2h, W2l,
                                           sWh, sWl, tid, acc);
        epi_to_smem<H2, (H2 == 128) ? 4 : 2>(acc, b2, sHh, sHl, H2 + 8, tid);
        __syncthreads();
        mlp_phase<HOUT, (HOUT == 128) ? 4 : 2>(sHh, sHl, H2 + 8, H2, W3h, W3l,
                                               sWh, sWl, tid, acc);
        epi_to_global<HOUT, (HOUT == 128) ? 4 : 2>(acc, b3, OUT, M, row0, tid,
                                                   sOut, statc0);
    }

    // ---- block-level pair-norm moments (deterministic partials) ----
    if (gid != 0) {
        __syncthreads();
        int f = tid & 63;
        int rs = tid >> 6;
        int gA = sGid[0];
        int gB = sMeta[0];
        float s1a = 0.f, s2a = 0.f, s1b = 0.f, s2b = 0.f;
        for (int rr = 0; rr < 32; rr++) {
            int r = rs * 32 + rr;
            int gg = sGid[r];
            float x = sOut[r * 64 + f];
            if (gg == gA) {
                s1a += x;
                s2a += x * x;
            } else if (gg == gB) {
                s1b += x;
                s2b += x * x;
            }
        }
        float* sc = (float*)sWh;
        sc[(0 * 4 + rs) * 64 + f] = s1a;
        sc[(1 * 4 + rs) * 64 + f] = s2a;
        sc[(2 * 4 + rs) * 64 + f] = s1b;
        sc[(3 * 4 + rs) * 64 + f] = s2b;
        __syncthreads();
        if (tid < 64) {
            float a1 = sc[0 * 64 + tid] + sc[1 * 64 + tid] + sc[2 * 64 + tid] + sc[3 * 64 + tid];
            float a2 = sc[4 * 64 + tid] + sc[5 * 64 + tid] + sc[6 * 64 + tid] + sc[7 * 64 + tid];
            float b1v = sc[8 * 64 + tid] + sc[9 * 64 + tid] + sc[10 * 64 + tid] + sc[11 * 64 + tid];
            float b2v = sc[12 * 64 + tid] + sc[13 * 64 + tid] + sc[14 * 64 + tid] + sc[15 * 64 + tid];
            bsum[(size_t)blockIdx.x * 256 + tid] = a1;
            bsum[(size_t)blockIdx.x * 256 + 64 + tid] = a2;
            bsum[(size_t)blockIdx.x * 256 + 128 + tid] = b1v;
            bsum[(size_t)blockIdx.x * 256 + 192 + tid] = b2v;
        }
        if (tid == 0) {
            bgid[2 * blockIdx.x] = gA;
            bgid[2 * blockIdx.x + 1] = gB;
        }
    }
}

// group reduction over per-block partials (deterministic order)
__global__ void k_gred(const float* __restrict__ bsum,
                       const int* __restrict__ bgid,
                       const int* __restrict__ goff, int nblk) {
    int g = blockIdx.x;
    int f = threadIdx.x;
    int r0 = goff[g], r1 = goff[g + 1];
    float s1 = 0.f, s2 = 0.f;
    if (r1 > r0) {
        int b0 = r0 >> 7;
        int b1 = (r1 - 1) >> 7;
        for (int b = b0; b <= b1 && b < nblk; b++) {
            int ga = bgid[2 * b];
            int gb = bgid[2 * b + 1];
            if (ga == g) {
                s1 += bsum[(size_t)b * 256 + f];
                s2 += bsum[(size_t)b * 256 + 64 + f];
            }
            if (gb == g && gb != ga) {
                s1 += bsum[(size_t)b * 256 + 128 + f];
                s2 += bsum[(size_t)b * 256 + 192 + f];
            }
        }
    }
    float cnt = fmaxf((float)(r1 - r0), 1.f);
    float m = s1 / cnt;
    float var = fmaxf(s2 / cnt - m * m, 0.f);
    g_mean[g * 64 + f] = m;
    g_rstd[g * 64 + f] = rsqrtf(var + EPSV);
}

// ---------------- single-layer GEMM (o-MLP hidden only) ----------------
template <int BN>
__device__ __forceinline__ void tc_load(int k0, int tid, int row0, int M, int K0,
                                        const float* __restrict__ A0, int lda0,
                                        const __nv_bfloat16* __restrict__ Whi,
                                        const __nv_bfloat16* __restrict__ Wlo,
                                        float4* ar, uint4* wh, uint4* wl) {
    for (int i = 0; i < 4; i++) {
        int f = tid + i * 256;
        int r = f >> 3;
        int c4 = f & 7;
        int col = k0 + c4 * 4;
        int grow = row0 + r;
        float4 v = make_float4(0.f, 0.f, 0.f, 0.f);
        if (grow < M && col + 4 <= K0)
            v = *reinterpret_cast<const float4*>(A0 + (size_t)grow * lda0 + col);
        ar[i] = v;
    }
    const uint4* wh4 = reinterpret_cast<const uint4*>(Whi + (size_t)k0 * BN);
    const uint4* wl4 = reinterpret_cast<const uint4*>(Wlo + (size_t)k0 * BN);
    const int NW4 = BN / 64;
    for (int i = 0; i < NW4; i++) {
        wh[i] = wh4[tid + i * 256];
        wl[i] = wl4[tid + i * 256];
    }
}

template <int BN, int ACT>
__launch_bounds__(256, 1)
__global__ void k_tcgemm(int M, int K0, int Kpad,
                         const float* __restrict__ A0, int lda0,
                         const __nv_bfloat16* __restrict__ Whi,
                         const __nv_bfloat16* __restrict__ Wlo,
                         const float* __restrict__ bias,
                         float* __restrict__ C) {
    const int ASTR = 40;
    const int BSTR = BN + 8;
    const int WM = (BN == 128) ? 64 : 32;
    const int MT = WM / 16;
    const int NW4 = BN / 64;

    __shared__ __nv_bfloat16 Ash[128 * ASTR];
    __shared__ __nv_bfloat16 Asl[128 * ASTR];
    __shared__ __nv_bfloat16 Bsh[32 * (BN + 8)];
    __shared__ __nv_bfloat16 Bsl[32 * (BN + 8)];

    const int tid = threadIdx.x;
    const int lane = tid & 31;
    const int warp = tid >> 5;
    const int row0 = blockIdx.x * 128;
    int wm, wn;
    if (BN == 128) { wm = warp & 1; wn = warp >> 1; }
    else { wm = warp & 3; wn = warp >> 2; }
    const int wrow = wm * WM;
    const int wcol = wn * 32;

    float acc[MT][4][4];
#pragma unroll
    for (int i = 0; i < MT; i++)
#pragma unroll
        for (int j = 0; j < 4; j++)
#pragma unroll
            for (int q = 0; q < 4; q++) acc[i][j][q] = 0.f;

    const int S = Kpad / 32;
    float4 ar[4];
    uint4 wh[2], wl[2];
    tc_load<BN>(0, tid, row0, M, K0, A0, lda0, Whi, Wlo, ar, wh, wl);

    for (int s = 0; s < S; s++) {
#pragma unroll
        for (int i = 0; i < 4; i++) {
            int f = tid + i * 256;
            int r = f >> 3;
            int c4 = f & 7;
            float4 v = ar[i];
            __nv_bfloat16 h0, l0, h1, l1, h2, l2, h3, l3;
            bsplit(v.x, h0, l0);
            bsplit(v.y, h1, l1);
            bsplit(v.z, h2, l2);
            bsplit(v.w, h3, l3);
            __nv_bfloat16* ph = &Ash[r * ASTR + c4 * 4];
            __nv_bfloat16* pl = &Asl[r * ASTR + c4 * 4];
            ph[0] = h0; ph[1] = h1; ph[2] = h2; ph[3] = h3;
            pl[0] = l0; pl[1] = l1; pl[2] = l2; pl[3] = l3;
        }
#pragma unroll
        for (int i = 0; i < NW4; i++) {
            int f = tid + i * 256;
            int r = f / (BN / 8);
            int n8 = f % (BN / 8);
            *reinterpret_cast<uint4*>(&Bsh[r * BSTR + n8 * 8]) = wh[i];
            *reinterpret_cast<uint4*>(&Bsl[r * BSTR + n8 * 8]) = wl[i];
        }
        __syncthreads();
        if (s + 1 < S)
            tc_load<BN>((s + 1) * 32, tid, row0, M, K0, A0, lda0, Whi, Wlo, ar, wh, wl);

#pragma unroll
        for (int ks = 0; ks < 32; ks += 16) {
            u32 ah[MT][4], al[MT][4];
#pragma unroll
            for (int mt = 0; mt < MT; mt++) {
                int r = wrow + mt * 16 + (lane & 15);
                int kk = ks + ((lane >> 4) << 3);
                ldsm4(ah[mt][0], ah[mt][1], ah[mt][2], ah[mt][3],
                      smem_u32(&Ash[r * ASTR + kk]));
                ldsm4(al[mt][0], al[mt][1], al[mt][2], al[mt][3],
                      smem_u32(&Asl[r * ASTR + kk]));
            }
            u32 bh[4][2], bl[4][2];
#pragma unroll
            for (int half = 0; half < 2; half++) {
                int k = ks + (lane & 15);
                int n = wcol + half * 16 + ((lane >> 4) << 3);
                u32 r0, r1, r2, r3;
                ldsm4t(r0, r1, r2, r3, smem_u32(&Bsh[k * BSTR + n]));
                bh[half * 2 + 0][0] = r0;
                bh[half * 2 + 0][1] = r1;
                bh[half * 2 + 1][0] = r2;
                bh[half * 2 + 1][1] = r3;
                ldsm4t(r0, r1, r2, r3, smem_u32(&Bsl[k * BSTR + n]));
                bl[half * 2 + 0][0] = r0;
                bl[half * 2 + 0][1] = r1;
                bl[half * 2 + 1][0] = r2;
                bl[half * 2 + 1][1] = r3;
            }
#pragma unroll
            for (int mt = 0; mt < MT; mt++)
#pragma unroll
                for (int nt = 0; nt < 4; nt++) mma_bf16(acc[mt][nt], ah[mt], bh[nt]);
#pragma unroll
            for (int mt = 0; mt < MT; mt++)
#pragma unroll
                for (int nt = 0; nt < 4; nt++) mma_bf16(acc[mt][nt], ah[mt], bl[nt]);
#pragma unroll
            for (int mt = 0; mt < MT; mt++)
#pragma unroll
                for (int nt = 0; nt < 4; nt++) mma_bf16(acc[mt][nt], al[mt], bh[nt]);
        }
        __syncthreads();
    }

#pragma unroll
    for (int mt = 0; mt < MT; mt++) {
#pragma unroll
        for (int nt = 0; nt < 4; nt++) {
            int c = wcol + nt * 8 + (lane & 3) * 2;
            float b0 = bias[c];
            float b1 = bias[c + 1];
#pragma unroll
            for (int pr = 0; pr < 2; pr++) {
                int rr = row0 + wrow + mt * 16 + (lane >> 2) + pr * 8;
                if (rr < M) {
                    float v0 = acc[mt][nt][2 * pr + 0] + b0;
                    float v1 = acc[mt][nt][2 * pr + 1] + b1;
                    if (ACT) {
                        v0 = v0 > 0.f ? v0 : 0.2f * v0;
                        v1 = v1 > 0.f ? v1 : 0.2f * v1;
                    }
                    *reinterpret_cast<float2*>(C + (size_t)rr * BN + c) =
                        make_float2(v0, v1);
                }
            }
        }
    }
}

// ---------------- per-round fused kernels ----------------
__global__ void k_vmsg() {
    int t = blockIdx.x * 256 + threadIdx.x;
    int v = t >> 6;
    int f = t & 63;
    if (v >= NVV) return;
    float sp = 0.f, sn = 0.f, lp = 0.f, ln = 0.f;
    int e0 = g_off[v], e1 = g_off[v + 1];
    for (int i = e0; i < e1; i++) {
        int c = g_ecl[i];
        sp += g_cl[(size_t)c * 64 + f];
        lp += g_cdata[(size_t)c * 128 + f];
    }
    int n0 = g_off[NVV + v], n1 = g_off[NVV + v + 1];
    for (int i = n0; i < n1; i++) {
        int c = g_ecl[i];
        sn += g_cl[(size_t)c * 64 + f];
        ln += g_cdata[(size_t)c * 128 + f];
    }
    float q = g_query[(size_t)v * 64 + f];
    float sigp = 1.f / (1.f + expf(-q));
    float sign = 1.f / (1.f + expf(q));
    g_unit[(size_t)v * 256 + f] = g_vdw[v] * (sn * 0.25f * sign - sp * 0.25f * sigp);
    g_unit[(size_t)v * 256 + 128 + f] = lp * g_dw[v];
    g_unit[(size_t)v * 256 + 192 + f] = ln * g_dw[NVV + v];
}

__global__ void k_apply_c(const int* __restrict__ clause_gid) {
    int t = blockIdx.x * 256 + threadIdx.x;
    int r = t >> 6;
    int f = t & 63;
    if (r < NCC) {
        int g = clause_gid[r];
        float y = (g_cdata[(size_t)r * 128 + 64 + f] - g_mean[g * 64 + f]) *
                      g_rstd[g * 64 + f] * 0.25f +
                  0.1f * g_clauses[(size_t)r * 64 + f];
        g_clauses[(size_t)r * 64 + f] = y;
    }
}

__global__ void k_apply_v(const int* __restrict__ var_gid) {
    int t = blockIdx.x * 256 + threadIdx.x;
    int r = t >> 6;
    int f = t & 63;
    if (r < NVV) {
        int g = var_gid[r];
        float y = (g_uout[(size_t)r * 64 + f] - g_mean[g * 64 + f]) *
                      g_rstd[g * 64 + f] * 0.25f +
                  0.1f * g_variables[(size_t)r * 64 + f];
        g_variables[(size_t)r * 64 + f] = y;
        g_unit[(size_t)r * 256 + 64 + f] = y;
    }
}

__global__ void k_out(const float* __restrict__ oh,
                      const float* __restrict__ oW1,
                      const float* __restrict__ ob1,
                      float* __restrict__ out) {
    __shared__ float w[64];
    int tid = threadIdx.x;
    if (tid < 64) w[tid] = oW1[tid];
    __syncthreads();
    int warp = tid >> 5;
    int lane = tid & 31;
    int c = blockIdx.x * 8 + warp;
    if (c >= NCC) return;
    float s = oh[(size_t)c * 64 + lane] * w[lane] +
              oh[(size_t)c * 64 + 32 + lane] * w[32 + lane];
#pragma unroll
    for (int d = 16; d; d >>= 1) s += __shfl_down_sync(0xffffffffu, s, d);
    if (lane == 0) {
        float z = s + ob1[0];
        out[c] = 1.f / (1.f + expf(-z));
        out[NCC + c] = fmaxf(z, 0.f) + log1pf(expf(-fabsf(z)));
    }
}

// ---------------- host driver ----------------
extern "C" void kernel_launch(void* const* d_in, const int* in_sizes, int n_in,
                              void* d_out, int out_size) {
    const int*   lit_idx    = (const int*)d_in[0];
    const int*   var_gid    = (const int*)d_in[2];
    const int*   clause_gid = (const int*)d_in[3];
    const float* noise      = (const float*)d_in[4];
    const float* qW0 = (const float*)d_in[5];
    const float* qb0 = (const float*)d_in[6];
    const float* qW1 = (const float*)d_in[7];
    const float* qb1 = (const float*)d_in[8];
    const float* cW0 = (const float*)d_in[9];
    const float* cb0 = (const float*)d_in[10];
    const float* cW1 = (const float*)d_in[11];
    const float* cb1 = (const float*)d_in[12];
    const float* uW0 = (const float*)d_in[13];
    const float* ub0 = (const float*)d_in[14];
    const float* uW1 = (const float*)d_in[15];
    const float* ub1 = (const float*)d_in[16];
    const float* uW2 = (const float*)d_in[17];
    const float* ub2 = (const float*)d_in[18];
    const float* oW0 = (const float*)d_in[19];
    const float* ob0 = (const float*)d_in[20];
    const float* oW1 = (const float*)d_in[21];
    const float* ob1 = (const float*)d_in[22];
    float* out = (float*)d_out;

    float* p_vars = 0;
    float* p_clauses = 0;
    float* p_unit = 0;
    float* p_cdata = 0;
    float* p_cl = 0;
    float* p_ch = 0;
    float* p_query = 0;
    float* p_uout = 0;
    int* p_goff_v = 0;
    int* p_goff_c = 0;
    float* p_bsum = 0;
    int* p_bgid = 0;
    __nv_bfloat16* p_whi = 0;
    __nv_bfloat16* p_wlo = 0;
    cudaGetSymbolAddress((void**)&p_vars, g_variables);
    cudaGetSymbolAddress((void**)&p_clauses, g_clauses);
    cudaGetSymbolAddress((void**)&p_unit, g_unit);
    cudaGetSymbolAddress((void**)&p_cdata, g_cdata);
    cudaGetSymbolAddress((void**)&p_cl, g_cl);
    cudaGetSymbolAddress((void**)&p_ch, g_ch);
    cudaGetSymbolAddress((void**)&p_query, g_query);
    cudaGetSymbolAddress((void**)&p_uout, g_uout);
    cudaGetSymbolAddress((void**)&p_goff_v, g_goff_v);
    cudaGetSymbolAddress((void**)&p_goff_c, g_goff_c);
    cudaGetSymbolAddress((void**)&p_bsum, g_bsum);
    cudaGetSymbolAddress((void**)&p_bgid, g_bgid);
    cudaGetSymbolAddress((void**)&p_whi, g_whi);
    cudaGetSymbolAddress((void**)&p_wlo, g_wlo);

    cudaFuncSetAttribute(k_mlp<3, 1, 64, 2, 0, 64, 0>,
                         cudaFuncAttributeMaxDynamicSharedMemorySize, SMEMSZ);
    cudaFuncSetAttribute(k_mlp<4, 2, 128, 2, 0, 128, 1>,
                         cudaFuncAttributeMaxDynamicSharedMemorySize, SMEMSZ);
    cudaFuncSetAttribute(k_mlp<4, 2, 128, 2, 0, 128, 0>,
                         cudaFuncAttributeMaxDynamicSharedMemorySize, SMEMSZ);
    cudaFuncSetAttribute(k_mlp<8, 0, 128, 3, 128, 64, 0>,
                         cudaFuncAttributeMaxDynamicSharedMemorySize, SMEMSZ);

    // ---- setup: 3 launches; launch #4 = q-MLP (profiled) ----
    k_setup_init<<<cdiv(NCC * 64, 256), 256>>>(qW0, qW1, cW0, cW1, uW0, uW1, uW2, oW0);
    k_countall<<<cdiv(NEE, 256), 256>>>(lit_idx, var_gid, clause_gid);
    k_scan<<<1, 1024>>>();

    const int GV = cdiv(NVV, 128);
    const int GC = cdiv(NCC, 128);
    const float* fnull = 0;
    const int* inull = 0;
    const __nv_bfloat16* bnull = 0;

    for (int t = 0; t < RNDS; t++) {
        const float* noise_t = noise + (size_t)t * NVV * 4;
        bool last = (t == RNDS - 1);

        // q-MLP: [vars|noise] -> query (no stats)
        k_mlp<3, 1, 64, 2, 0, 64, 0><<<GV, 256, SMEMSZ>>>(
            NVV, p_vars, 64, noise_t, inull, fnull, (float*)0,
            inull, (float*)0, (int*)0, 0,
            p_whi + OQ0, p_wlo + OQ0, qb0,
            p_whi + OQ1, p_wlo + OQ1, qb1,
            bnull, bnull, fnull, p_query);

        // c-MLP: [clauses | 4*exp(-cv)] -> cdata (+ g_cl) + block stats of cols 64-127
        if (!last) {
            k_mlp<4, 2, 128, 2, 0, 128, 1><<<GC, 256, SMEMSZ>>>(
                NCC, p_clauses, 64, fnull, lit_idx, p_query, p_cl,
                clause_gid, p_bsum, p_bgid, 64,
                p_whi + OC0, p_wlo + OC0, cb0,
                p_whi + OC1, p_wlo + OC1, cb1,
                bnull, bnull, fnull, p_cdata);
        } else {
            k_mlp<4, 2, 128, 2, 0, 128, 0><<<GC, 256, SMEMSZ>>>(
                NCC, p_clauses, 64, fnull, lit_idx, p_query, (float*)0,
                clause_gid, p_bsum, p_bgid, 64,
                p_whi + OC0, p_wlo + OC0, cb0,
                p_whi + OC1, p_wlo + OC1, cb1,
                bnull, bnull, fnull, p_cdata);
        }

        if (t == 0)
            k_fill<<<cdiv(NEE, 256), 256>>>(lit_idx);

        if (!last) {
            k_vmsg<<<VMB, 256>>>();
            k_gred<<<NGG, 64>>>(p_bsum, p_bgid, p_goff_c, GC);
            k_apply_c<<<cdiv(NCC * 64, 256), 256>>>(clause_gid);

            // u-MLP: unit(256) -> 128 -> 128 -> 64 + block stats of all 64 cols
            k_mlp<8, 0, 128, 3, 128, 64, 0><<<GV, 256, SMEMSZ>>>(
                NVV, p_unit, 256, fnull, inull, fnull, (float*)0,
                var_gid, p_bsum, p_bgid, 0,
                p_whi + OU0, p_wlo + OU0, ub0,
                p_whi + OU1, p_wlo + OU1, ub1,
                p_whi + OU2, p_wlo + OU2, ub2, p_uout);
            k_gred<<<NGG, 64>>>(p_bsum, p_bgid, p_goff_v, GV);
            k_apply_v<<<cdiv(NVV * 64, 256), 256>>>(var_gid);
        } else {
            k_gred<<<NGG, 64>>>(p_bsum, p_bgid, p_goff_c, GC);
            k_apply_c<<<cdiv(NCC * 64, 256), 256>>>(clause_gid);
        }
    }

    // output head
    k_tcgemm<64, 1><<<GC, 256>>>(NCC, 64, 64, p_clauses, 64,
                                 p_whi + OO0, p_wlo + OO0, ob0, p_ch);
    k_out<<<cdiv(NCC, 8), 256>>>(p_ch, oW1, ob1, out);
}

// round 12
// speedup vs baseline: 1.2640x; 1.2640x over previous
#include <cuda_runtime.h>
#include <cuda_bf16.h>
#include <cstdint>
#include <math.h>

typedef unsigned int u32;

#define NVV 50000
#define NCC 210000
#define NEE 630000
#define NGG 32
#define RNDS 16
#define PNB 16
#define EPSV 1e-6f

// ---------------- scratch (static device globals; no allocation) ----------------
__device__ float g_variables[NVV * 64];
__device__ float g_clauses[NCC * 64];
__device__ float g_unit[NVV * 256];
__device__ float g_cdata[NCC * 128];
__device__ float g_cl[NCC * 64];
__device__ float g_ch[NCC * 64];
__device__ float g_query[NVV * 64];
__device__ float g_uout[NVV * 64];

__device__ int   g_cnt[2 * NVV];
__device__ int   g_off[2 * NVV + 1];
__device__ int   g_cur[2 * NVV];
__device__ int   g_ecl[NEE];
__device__ float g_dw[2 * NVV];
__device__ float g_vdw[NVV];
__device__ int   g_gcnt_v[NGG];
__device__ int   g_gcnt_c[NGG];
__device__ int   g_goff_v[NGG + 1];
__device__ int   g_goff_c[NGG + 1];
__device__ float g_psum[NGG * PNB * 128];
__device__ float g_mean[NGG * 64];
__device__ float g_rstd[NGG * 64];

#define OQ0 0
#define OQ1 6144
#define OC0 10240
#define OC1 26624
#define OU0 43008
#define OU1 75776
#define OU2 92160
#define OO0 100352
#define WPOOL 104448
__device__ __nv_bfloat16 g_whi[WPOOL];
__device__ __nv_bfloat16 g_wlo[WPOOL];

// per-config dynamic smem sizes (bytes)
#define SM_Q 67072
#define SM_C 109568
#define SM_U 108032

static inline int cdiv(int a, int b) { return (a + b - 1) / b; }

// ---------------- setup ----------------
__global__ void k_setup_init() {
    int i = blockIdx.x * 256 + threadIdx.x;
    if (i < NCC * 64) g_clauses[i] = 1.f;
    if (i < NVV * 64) {
        g_variables[i] = 1.f;
        int r = i >> 6;
        int c = i & 63;
        g_unit[r * 256 + 64 + c] = 1.f;
    }
    if (i < 2 * NVV) g_cnt[i] = 0;
    if (i < NGG) {
        g_gcnt_v[i] = 0;
        g_gcnt_c[i] = 0;
    }
}

__global__ void k_countall(const int* __restrict__ lit_idx,
                           const int* __restrict__ var_gid,
                           const int* __restrict__ clause_gid) {
    int i = blockIdx.x * 256 + threadIdx.x;
    if (i < NEE) atomicAdd(&g_cnt[lit_idx[i]], 1);
    if (i < NVV) atomicAdd(&g_gcnt_v[var_gid[i]], 1);
    if (i < NCC) atomicAdd(&g_gcnt_c[clause_gid[i]], 1);
}

__global__ void k_scan() {
    __shared__ int ssum[1024];
    int tid = threadIdx.x;
    const int Ntot = 2 * NVV;
    int chunk = (Ntot + 1023) / 1024;
    int base = tid * chunk;
    int s = 0;
    for (int i = 0; i < chunk; i++) {
        int idx = base + i;
        if (idx < Ntot) s += g_cnt[idx];
    }
    ssum[tid] = s;
    __syncthreads();
    for (int d = 1; d < 1024; d <<= 1) {
        int v = (tid >= d) ? ssum[tid - d] : 0;
        __syncthreads();
        ssum[tid] += v;
        __syncthreads();
    }
    int run = (tid == 0) ? 0 : ssum[tid - 1];
    for (int i = 0; i < chunk; i++) {
        int idx = base + i;
        if (idx < Ntot) {
            g_off[idx] = run;
            g_cur[idx] = run;
            int c = g_cnt[idx];
            g_dw[idx] = rsqrtf(fmaxf((float)c, 1.f));
            run += c;
        }
    }
    if (tid == 1023) g_off[Ntot] = ssum[1023];
    if (tid == 0) {
        int a = 0;
        for (int g = 0; g < NGG; g++) {
            g_goff_v[g] = a;
            a += g_gcnt_v[g];
        }
        g_goff_v[NGG] = a;
        int b = 0;
        for (int g = 0; g < NGG; g++) {
            g_goff_c[g] = b;
            b += g_gcnt_c[g];
        }
        g_goff_c[NGG] = b;
    }
    __syncthreads();
    for (int v = tid; v < NVV; v += 1024)
        g_vdw[v] = 4.f * rsqrtf(fmaxf((float)(g_cnt[v] + g_cnt[NVV + v]), 1.f));
}

__global__ void k_fill(const int* __restrict__ lit_idx) {
    int e = blockIdx.x * 256 + threadIdx.x;
    if (e < NEE) {
        int p = atomicAdd(&g_cur[lit_idx[e]], 1);
        g_ecl[p] = e / 3;
    }
}

__global__ void k_wsplit_all(const float* __restrict__ qW0, const float* __restrict__ qW1,
                             const float* __restrict__ cW0, const float* __restrict__ cW1,
                             const float* __restrict__ uW0, const float* __restrict__ uW1,
                             const float* __restrict__ uW2, const float* __restrict__ oW0) {
    int i = blockIdx.x * 256 + threadIdx.x;
    if (i >= WPOOL) return;
    const float* W;
    int K, N, local;
    if (i < OQ1)      { W = qW0; K = 68;  N = 64;  local = i - OQ0; }
    else if (i < OC0) { W = qW1; K = 64;  N = 64;  local = i - OQ1; }
    else if (i < OC1) { W = cW0; K = 128; N = 128; local = i - OC0; }
    else if (i < OU0) { W = cW1; K = 128; N = 128; local = i - OC1; }
    else if (i < OU1) { W = uW0; K = 256; N = 128; local = i - OU0; }
    else if (i < OU2) { W = uW1; K = 128; N = 128; local = i - OU1; }
    else if (i < OO0) { W = uW2; K = 128; N = 64;  local = i - OU2; }
    else              { W = oW0; K = 64;  N = 64;  local = i - OO0; }
    int k = local / N;
    float v = (k < K) ? W[local] : 0.f;
    __nv_bfloat16 h = __float2bfloat16(v);
    g_whi[i] = h;
    g_wlo[i] = __float2bfloat16(v - __bfloat162float(h));
}

// ---------------- MMA helpers ----------------
__device__ __forceinline__ u32 smem_u32(const void* p) {
    return (u32)__cvta_generic_to_shared(p);
}

__device__ __forceinline__ void ldsm4(u32& r0, u32& r1, u32& r2, u32& r3, u32 a) {
    asm volatile("ldmatrix.sync.aligned.m8n8.x4.shared.b16 {%0,%1,%2,%3}, [%4];"
                 : "=r"(r0), "=r"(r1), "=r"(r2), "=r"(r3) : "r"(a));
}

__device__ __forceinline__ void ldsm4t(u32& r0, u32& r1, u32& r2, u32& r3, u32 a) {
    asm volatile("ldmatrix.sync.aligned.m8n8.x4.trans.shared.b16 {%0,%1,%2,%3}, [%4];"
                 : "=r"(r0), "=r"(r1), "=r"(r2), "=r"(r3) : "r"(a));
}

__device__ __forceinline__ void mma_bf16(float* c, const u32* a, const u32* b) {
    asm volatile(
        "mma.sync.aligned.m16n8k16.row.col.f32.bf16.bf16.f32 "
        "{%0,%1,%2,%3}, {%4,%5,%6,%7}, {%8,%9}, {%0,%1,%2,%3};"
        : "+f"(c[0]), "+f"(c[1]), "+f"(c[2]), "+f"(c[3])
        : "r"(a[0]), "r"(a[1]), "r"(a[2]), "r"(a[3]), "r"(b[0]), "r"(b[1]));
}

__device__ __forceinline__ float softplusf(float x) {
    return fmaxf(x, 0.f) + log1pf(expf(-fabsf(x)));
}

__device__ __forceinline__ void bsplit(float v, __nv_bfloat16& h, __nv_bfloat16& l) {
    h = __float2bfloat16(v);
    l = __float2bfloat16(v - __bfloat162float(h));
}

template <int NW>
__device__ __forceinline__ void wload(int s, int tid,
                                      const __nv_bfloat16* __restrict__ Wh,
                                      const __nv_bfloat16* __restrict__ Wl,
                                      uint4* th, uint4* tl) {
    const uint4* wh4 = reinterpret_cast<const uint4*>(Wh + (size_t)s * 32 * NW);
    const uint4* wl4 = reinterpret_cast<const uint4*>(Wl + (size_t)s * 32 * NW);
    const int NW4 = NW / 64;
    for (int i = 0; i < NW4; i++) {
        th[i] = wh4[tid + i * 256];
        tl[i] = wl4[tid + i * 256];
    }
}

template <int NW, int MT>
__device__ __forceinline__ void mlp_phase(const __nv_bfloat16* Hh, const __nv_bfloat16* Hl,
                                          int hstr, int Kdim,
                                          const __nv_bfloat16* __restrict__ Wh,
                                          const __nv_bfloat16* __restrict__ Wl,
                                          __nv_bfloat16* sWh, __nv_bfloat16* sWl,
                                          int tid, float acc[][4][4]) {
    const int lane = tid & 31;
    const int warp = tid >> 5;
    int wm, wn;
    if (NW == 128) { wm = warp & 1; wn = warp >> 1; }
    else           { wm = warp & 3; wn = warp >> 2; }
    const int wrow = wm * 16 * MT;
    const int wcol = wn * 32;
    const int BSTR = NW + 8;
    const int NW4 = NW / 64;

#pragma unroll
    for (int i = 0; i < MT; i++)
#pragma unroll
        for (int j = 0; j < 4; j++)
#pragma unroll
            for (int q = 0; q < 4; q++) acc[i][j][q] = 0.f;

    uint4 th[2], tl[2];
    wload<NW>(0, tid, Wh, Wl, th, tl);
    const int S = Kdim / 32;
    for (int s = 0; s < S; s++) {
#pragma unroll
        for (int i = 0; i < NW4; i++) {
            int f = tid + i * 256;
            int r = f / (NW / 8);
            int n8 = f % (NW / 8);
            *reinterpret_cast<uint4*>(&sWh[r * BSTR + n8 * 8]) = th[i];
            *reinterpret_cast<uint4*>(&sWl[r * BSTR + n8 * 8]) = tl[i];
        }
        __syncthreads();
        if (s + 1 < S) wload<NW>(s + 1, tid, Wh, Wl, th, tl);
#pragma unroll
        for (int ks = 0; ks < 32; ks += 16) {
            int kk = s * 32 + ks;
            u32 ah[MT][4], al[MT][4];
#pragma unroll
            for (int mt = 0; mt < MT; mt++) {
                int r = wrow + mt * 16 + (lane & 15);
                int ko = kk + ((lane >> 4) << 3);
                ldsm4(ah[mt][0], ah[mt][1], ah[mt][2], ah[mt][3],
                      smem_u32(&Hh[r * hstr + ko]));
                ldsm4(al[mt][0], al[mt][1], al[mt][2], al[mt][3],
                      smem_u32(&Hl[r * hstr + ko]));
            }
            u32 bh[4][2], bl[4][2];
#pragma unroll
            for (int half = 0; half < 2; half++) {
                int k = ks + (lane & 15);
                int n = wcol + half * 16 + ((lane >> 4) << 3);
                u32 r0, r1, r2, r3;
                ldsm4t(r0, r1, r2, r3, smem_u32(&sWh[k * BSTR + n]));
                bh[half * 2 + 0][0] = r0;
                bh[half * 2 + 0][1] = r1;
                bh[half * 2 + 1][0] = r2;
                bh[half * 2 + 1][1] = r3;
                ldsm4t(r0, r1, r2, r3, smem_u32(&sWl[k * BSTR + n]));
                bl[half * 2 + 0][0] = r0;
                bl[half * 2 + 0][1] = r1;
                bl[half * 2 + 1][0] = r2;
                bl[half * 2 + 1][1] = r3;
            }
#pragma unroll
            for (int mt = 0; mt < MT; mt++)
#pragma unroll
                for (int nt = 0; nt < 4; nt++) mma_bf16(acc[mt][nt], ah[mt], bh[nt]);
#pragma unroll
            for (int mt = 0; mt < MT; mt++)
#pragma unroll
                for (int nt = 0; nt < 4; nt++) mma_bf16(acc[mt][nt], ah[mt], bl[nt]);
#pragma unroll
            for (int mt = 0; mt < MT; mt++)
#pragma unroll
                for (int nt = 0; nt < 4; nt++) mma_bf16(acc[mt][nt], al[mt], bh[nt]);
        }
        __syncthreads();
    }
}

template <int NW, int MT>
__device__ __forceinline__ void epi_to_smem(float acc[][4][4],
                                            const float* __restrict__ bias,
                                            __nv_bfloat16* Hh, __nv_bfloat16* Hl,
                                            int hstr, int tid) {
    const int lane = tid & 31;
    const int warp = tid >> 5;
    int wm, wn;
    if (NW == 128) { wm = warp & 1; wn = warp >> 1; }
    else           { wm = warp & 3; wn = warp >> 2; }
    const int wrow = wm * 16 * MT;
    const int wcol = wn * 32;
#pragma unroll
    for (int mt = 0; mt < MT; mt++) {
#pragma unroll
        for (int nt = 0; nt < 4; nt++) {
            int c = wcol + nt * 8 + (lane & 3) * 2;
            float b0 = bias[c];
            float b1 = bias[c + 1];
#pragma unroll
            for (int pr = 0; pr < 2; pr++) {
                int r = wrow + mt * 16 + (lane >> 2) + pr * 8;
                float v0 = acc[mt][nt][2 * pr + 0] + b0;
                float v1 = acc[mt][nt][2 * pr + 1] + b1;
                v0 = v0 > 0.f ? v0 : 0.2f * v0;
                v1 = v1 > 0.f ? v1 : 0.2f * v1;
                __nv_bfloat16 h0, l0, h1, l1;
                bsplit(v0, h0, l0);
                bsplit(v1, h1, l1);
                Hh[r * hstr + c] = h0;
                Hh[r * hstr + c + 1] = h1;
                Hl[r * hstr + c] = l0;
                Hl[r * hstr + c + 1] = l1;
            }
        }
    }
}

template <int NW, int MT>
__device__ __forceinline__ void epi_to_global(float acc[][4][4],
                                              const float* __restrict__ bias,
                                              float* __restrict__ OUT, int M,
                                              int row0, int tid) {
    const int lane = tid & 31;
    const int warp = tid >> 5;
    int wm, wn;
    if (NW == 128) { wm = warp & 1; wn = warp >> 1; }
    else           { wm = warp & 3; wn = warp >> 2; }
    const int wrow = wm * 16 * MT;
    const int wcol = wn * 32;
#pragma unroll
    for (int mt = 0; mt < MT; mt++) {
#pragma unroll
        for (int nt = 0; nt < 4; nt++) {
            int c = wcol + nt * 8 + (lane & 3) * 2;
            float b0 = bias[c];
            float b1 = bias[c + 1];
#pragma unroll
            for (int pr = 0; pr < 2; pr++) {
                int rr = row0 + wrow + mt * 16 + (lane >> 2) + pr * 8;
                if (rr < M) {
                    float v0 = acc[mt][nt][2 * pr + 0] + b0;
                    float v1 = acc[mt][nt][2 * pr + 1] + b1;
                    *reinterpret_cast<float2*>(OUT + (size_t)rr * NW + c) =
                        make_float2(v0, v1);
                }
            }
        }
    }
}

// ---------------- fused multi-layer MLP kernel (templated smem layout) -------
// MODE 0: A = A0[M, lda0]; MODE 1: [vars|noise]; MODE 2: [clauses | 4*exp(-cv)]
template <int K1S, int MODE, int H1, int NL, int H2, int HOUT, int WCL>
__launch_bounds__(256)
__global__ void k_mlp(int M,
                      const float* __restrict__ A0, int lda0,
                      const float* __restrict__ A1,
                      const int* __restrict__ lit,
                      const float* __restrict__ query,
                      float* __restrict__ clout,
                      const __nv_bfloat16* __restrict__ W1h,
                      const __nv_bfloat16* __restrict__ W1l,
                      const float* __restrict__ b1,
                      const __nv_bfloat16* __restrict__ W2h,
                      const __nv_bfloat16* __restrict__ W2l,
                      const float* __restrict__ b2,
                      const __nv_bfloat16* __restrict__ W3h,
                      const __nv_bfloat16* __restrict__ W3l,
                      const float* __restrict__ b3,
                      float* __restrict__ OUT) {
    extern __shared__ char smem[];
    const int ASTR = 40;
    // template-derived smem strides: capacity for widest N used by this config
    const int M2X = (NL == 2) ? HOUT : H2;
    const int NM0 = (H1 > M2X) ? H1 : M2X;
    const int NMX = (NM0 > HOUT) ? NM0 : HOUT;
    const int WS = NMX + 8;
    __nv_bfloat16* sAh = (__nv_bfloat16*)smem;           // 128*40
    __nv_bfloat16* sAl = sAh + 128 * ASTR;
    __nv_bfloat16* sWh = sAl + 128 * ASTR;               // 32*WS
    __nv_bfloat16* sWl = sWh + 32 * WS;
    __nv_bfloat16* sHh = sWl + 32 * WS;                  // 128*WS
    __nv_bfloat16* sHl = sHh + 128 * WS;
    int* sLit = (int*)(sHl + 128 * WS);                  // 128*3 (MODE 2 only)

    const int tid = threadIdx.x;
    const int lane = tid & 31;
    const int warp = tid >> 5;
    const int row0 = blockIdx.x * 128;
    const int HSTR1 = H1 + 8;

    if (MODE == 2) {
        for (int i = tid; i < 128 * 3; i += 256) {
            int r = i / 3;
            int j = i % 3;
            int row = row0 + r;
            sLit[i] = (row < M) ? lit[row * 3 + j] : 0;
        }
    }
    __syncthreads();

    const int MT1 = (H1 == 128) ? 4 : 2;
    int wm1, wn1;
    if (H1 == 128) { wm1 = warp & 1; wn1 = warp >> 1; }
    else           { wm1 = warp & 3; wn1 = warp >> 2; }
    const int wrow1 = wm1 * 16 * MT1;
    const int wcol1 = wn1 * 32;
    const int BSTR1 = H1 + 8;
    const int NW41 = H1 / 64;

    float acc[4][4][4];
#pragma unroll
    for (int i = 0; i < MT1; i++)
#pragma unroll
        for (int j = 0; j < 4; j++)
#pragma unroll
            for (int q = 0; q < 4; q++) acc[i][j][q] = 0.f;

    for (int s = 0; s < K1S; s++) {
        float4 ar[4];
#pragma unroll
        for (int i = 0; i < 4; i++) {
            int f = tid + i * 256;
            int r = f >> 3;
            int c4 = f & 7;
            int col = s * 32 + c4 * 4;
            int row = row0 + r;
            float4 v = make_float4(0.f, 0.f, 0.f, 0.f);
            if (row < M) {
                if (MODE == 0) {
                    v = *reinterpret_cast<const float4*>(A0 + (size_t)row * lda0 + col);
                } else if (MODE == 1) {
                    if (col < 64)
                        v = *reinterpret_cast<const float4*>(A0 + (size_t)row * 64 + col);
                    else if (col == 64)
                        v = *reinterpret_cast<const float4*>(A1 + (size_t)row * 4);
                } else {
                    if (s < 2) {
                        v = *reinterpret_cast<const float4*>(A0 + (size_t)row * 64 + col);
                    } else {
                        int fc = col - 64;
                        float cv0 = 0.f, cv1 = 0.f, cv2 = 0.f, cv3 = 0.f;
#pragma unroll
                        for (int j = 0; j < 3; j++) {
                            int l = sLit[r * 3 + j];
                            int qr = (l < NVV) ? l : (l - NVV);
                            float sg = (l < NVV) ? 1.f : -1.f;
                            float4 qv = *reinterpret_cast<const float4*>(
                                query + (size_t)qr * 64 + fc);
                            cv0 += softplusf(sg * qv.x);
                            cv1 += softplusf(sg * qv.y);
                            cv2 += softplusf(sg * qv.z);
                            cv3 += softplusf(sg * qv.w);
                        }
                        v = make_float4(4.f * expf(-cv0), 4.f * expf(-cv1),
                                        4.f * expf(-cv2), 4.f * expf(-cv3));
                        if (WCL)
                            *reinterpret_cast<float4*>(clout + (size_t)row * 64 + fc) = v;
                    }
                }
            }
            ar[i] = v;
        }
        uint4 th[2], tl[2];
        const uint4* wh4 = reinterpret_cast<const uint4*>(W1h + (size_t)s * 32 * H1);
        const uint4* wl4 = reinterpret_cast<const uint4*>(W1l + (size_t)s * 32 * H1);
#pragma unroll
        for (int i = 0; i < NW41; i++) {
            th[i] = wh4[tid + i * 256];
            tl[i] = wl4[tid + i * 256];
        }
        __syncthreads();
#pragma unroll
        for (int i = 0; i < 4; i++) {
            int f = tid + i * 256;
            int r = f >> 3;
            int c4 = f & 7;
            float4 v = ar[i];
            __nv_bfloat16 h0, l0, h1, l1, h2, l2, h3, l3;
            bsplit(v.x, h0, l0);
            bsplit(v.y, h1, l1);
            bsplit(v.z, h2, l2);
            bsplit(v.w, h3, l3);
            __nv_bfloat16* ph = &sAh[r * ASTR + c4 * 4];
            __nv_bfloat16* pl = &sAl[r * ASTR + c4 * 4];
            ph[0] = h0; ph[1] = h1; ph[2] = h2; ph[3] = h3;
            pl[0] = l0; pl[1] = l1; pl[2] = l2; pl[3] = l3;
        }
#pragma unroll
        for (int i = 0; i < NW41; i++) {
            int f = tid + i * 256;
            int r = f / (H1 / 8);
            int n8 = f % (H1 / 8);
            *reinterpret_cast<uint4*>(&sWh[r * BSTR1 + n8 * 8]) = th[i];
            *reinterpret_cast<uint4*>(&sWl[r * BSTR1 + n8 * 8]) = tl[i];
        }
        __syncthreads();
#pragma unroll
        for (int ks = 0; ks < 32; ks += 16) {
            u32 ah[4][4], al[4][4];
#pragma unroll
            for (int mt = 0; mt < MT1; mt++) {
                int r = wrow1 + mt * 16 + (lane & 15);
                int ko = ks + ((lane >> 4) << 3);
                ldsm4(ah[mt][0], ah[mt][1], ah[mt][2], ah[mt][3],
                      smem_u32(&sAh[r * ASTR + ko]));
                ldsm4(al[mt][0], al[mt][1], al[mt][2], al[mt][3],
                      smem_u32(&sAl[r * ASTR + ko]));
            }
            u32 bh[4][2], bl[4][2];
#pragma unroll
            for (int half = 0; half < 2; half++) {
                int k = ks + (lane & 15);
                int n = wcol1 + half * 16 + ((lane >> 4) << 3);
                u32 r0, r1, r2, r3;
                ldsm4t(r0, r1, r2, r3, smem_u32(&sWh[k * BSTR1 + n]));
                bh[half * 2 + 0][0] = r0;
                bh[half * 2 + 0][1] = r1;
                bh[half * 2 + 1][0] = r2;
                bh[half * 2 + 1][1] = r3;
                ldsm4t(r0, r1, r2, r3, smem_u32(&sWl[k * BSTR1 + n]));
                bl[half * 2 + 0][0] = r0;
                bl[half * 2 + 0][1] = r1;
                bl[half * 2 + 1][0] = r2;
                bl[half * 2 + 1][1] = r3;
            }
#pragma unroll
            for (int mt = 0; mt < MT1; mt++)
#pragma unroll
                for (int nt = 0; nt < 4; nt++) mma_bf16(acc[mt][nt], ah[mt], bh[nt]);
#pragma unroll
            for (int mt = 0; mt < MT1; mt++)
#pragma unroll
                for (int nt = 0; nt < 4; nt++) mma_bf16(acc[mt][nt], ah[mt], bl[nt]);
#pragma unroll
            for (int mt = 0; mt < MT1; mt++)
#pragma unroll
                for (int nt = 0; nt < 4; nt++) mma_bf16(acc[mt][nt], al[mt], bh[nt]);
        }
        __syncthreads();
    }
    epi_to_smem<H1, (H1 == 128) ? 4 : 2>(acc, b1, sHh, sHl, HSTR1, tid);
    __syncthreads();

    if (NL == 2) {
        mlp_phase<HOUT, (HOUT == 128) ? 4 : 2>(sHh, sHl, HSTR1, H1, W2h, W2l,
                                               sWh, sWl, tid, acc);
        epi_to_global<HOUT, (HOUT == 128) ? 4 : 2>(acc, b2, OUT, M, row0, tid);
    } else {
        mlp_phase<H2, (H2 == 128) ? 4 : 2>(sHh, sHl, HSTR1, H1, W2h, W2l,
                                           sWh, sWl, tid, acc);
        epi_to_smem<H2, (H2 == 128) ? 4 : 2>(acc, b2, sHh, sHl, H2 + 8, tid);
        __syncthreads();
        mlp_phase<HOUT, (HOUT == 128) ? 4 : 2>(sHh, sHl, H2 + 8, H2, W3h, W3l,
                                               sWh, sWl, tid, acc);
        epi_to_global<HOUT, (HOUT == 128) ? 4 : 2>(acc, b3, OUT, M, row0, tid);
    }
}

// ---------------- single-layer GEMM (o-MLP hidden only) ----------------
template <int BN>
__device__ __forceinline__ void tc_load(int k0, int tid, int row0, int M, int K0,
                                        const float* __restrict__ A0, int lda0,
                                        const __nv_bfloat16* __restrict__ Whi,
                                        const __nv_bfloat16* __restrict__ Wlo,
                                        float4* ar, uint4* wh, uint4* wl) {
    for (int i = 0; i < 4; i++) {
        int f = tid + i * 256;
        int r = f >> 3;
        int c4 = f & 7;
        int col = k0 + c4 * 4;
        int grow = row0 + r;
        float4 v = make_float4(0.f, 0.f, 0.f, 0.f);
        if (grow < M && col + 4 <= K0)
            v = *reinterpret_cast<const float4*>(A0 + (size_t)grow * lda0 + col);
        ar[i] = v;
    }
    const uint4* wh4 = reinterpret_cast<const uint4*>(Whi + (size_t)k0 * BN);
    const uint4* wl4 = reinterpret_cast<const uint4*>(Wlo + (size_t)k0 * BN);
    const int NW4 = BN / 64;
    for (int i = 0; i < NW4; i++) {
        wh[i] = wh4[tid + i * 256];
        wl[i] = wl4[tid + i * 256];
    }
}

template <int BN, int ACT>
__launch_bounds__(256)
__global__ void k_tcgemm(int M, int K0, int Kpad,
                         const float* __restrict__ A0, int lda0,
                         const __nv_bfloat16* __restrict__ Whi,
                         const __nv_bfloat16* __restrict__ Wlo,
                         const float* __restrict__ bias,
                         float* __restrict__ C) {
    const int ASTR = 40;
    const int BSTR = BN + 8;
    const int WM = (BN == 128) ? 64 : 32;
    const int MT = WM / 16;
    const int NW4 = BN / 64;

    __shared__ __nv_bfloat16 Ash[128 * ASTR];
    __shared__ __nv_bfloat16 Asl[128 * ASTR];
    __shared__ __nv_bfloat16 Bsh[32 * (BN + 8)];
    __shared__ __nv_bfloat16 Bsl[32 * (BN + 8)];

    const int tid = threadIdx.x;
    const int lane = tid & 31;
    const int warp = tid >> 5;
    const int row0 = blockIdx.x * 128;
    int wm, wn;
    if (BN == 128) { wm = warp & 1; wn = warp >> 1; }
    else { wm = warp & 3; wn = warp >> 2; }
    const int wrow = wm * WM;
    const int wcol = wn * 32;

    float acc[MT][4][4];
#pragma unroll
    for (int i = 0; i < MT; i++)
#pragma unroll
        for (int j = 0; j < 4; j++)
#pragma unroll
            for (int q = 0; q < 4; q++) acc[i][j][q] = 0.f;

    const int S = Kpad / 32;
    float4 ar[4];
    uint4 wh[2], wl[2];
    tc_load<BN>(0, tid, row0, M, K0, A0, lda0, Whi, Wlo, ar, wh, wl);

    for (int s = 0; s < S; s++) {
#pragma unroll
        for (int i = 0; i < 4; i++) {
            int f = tid + i * 256;
            int r = f >> 3;
            int c4 = f & 7;
            float4 v = ar[i];
            __nv_bfloat16 h0, l0, h1, l1, h2, l2, h3, l3;
            bsplit(v.x, h0, l0);
            bsplit(v.y, h1, l1);
            bsplit(v.z, h2, l2);
            bsplit(v.w, h3, l3);
            __nv_bfloat16* ph = &Ash[r * ASTR + c4 * 4];
            __nv_bfloat16* pl = &Asl[r * ASTR + c4 * 4];
            ph[0] = h0; ph[1] = h1; ph[2] = h2; ph[3] = h3;
            pl[0] = l0; pl[1] = l1; pl[2] = l2; pl[3] = l3;
        }
#pragma unroll
        for (int i = 0; i < NW4; i++) {
            int f = tid + i * 256;
            int r = f / (BN / 8);
            int n8 = f % (BN / 8);
            *reinterpret_cast<uint4*>(&Bsh[r * BSTR + n8 * 8]) = wh[i];
            *reinterpret_cast<uint4*>(&Bsl[r * BSTR + n8 * 8]) = wl[i];
        }
        __syncthreads();
        if (s + 1 < S)
            tc_load<BN>((s + 1) * 32, tid, row0, M, K0, A0, lda0, Whi, Wlo, ar, wh, wl);

#pragma unroll
        for (int ks = 0; ks < 32; ks += 16) {
            u32 ah[MT][4], al[MT][4];
#pragma unroll
            for (int mt = 0; mt < MT; mt++) {
                int r = wrow + mt * 16 + (lane & 15);
                int kk = ks + ((lane >> 4) << 3);
                ldsm4(ah[mt][0], ah[mt][1], ah[mt][2], ah[mt][3],
                      smem_u32(&Ash[r * ASTR + kk]));
                ldsm4(al[mt][0], al[mt][1], al[mt][2], al[mt][3],
                      smem_u32(&Asl[r * ASTR + kk]));
            }
            u32 bh[4][2], bl[4][2];
#pragma unroll
            for (int half = 0; half < 2; half++) {
                int k = ks + (lane & 15);
                int n = wcol + half * 16 + ((lane >> 4) << 3);
                u32 r0, r1, r2, r3;
                ldsm4t(r0, r1, r2, r3, smem_u32(&Bsh[k * BSTR + n]));
                bh[half * 2 + 0][0] = r0;
                bh[half * 2 + 0][1] = r1;
                bh[half * 2 + 1][0] = r2;
                bh[half * 2 + 1][1] = r3;
                ldsm4t(r0, r1, r2, r3, smem_u32(&Bsl[k * BSTR + n]));
                bl[half * 2 + 0][0] = r0;
                bl[half * 2 + 0][1] = r1;
                bl[half * 2 + 1][0] = r2;
                bl[half * 2 + 1][1] = r3;
            }
#pragma unroll
            for (int mt = 0; mt < MT; mt++)
#pragma unroll
                for (int nt = 0; nt < 4; nt++) mma_bf16(acc[mt][nt], ah[mt], bh[nt]);
#pragma unroll
            for (int mt = 0; mt < MT; mt++)
#pragma unroll
                for (int nt = 0; nt < 4; nt++) mma_bf16(acc[mt][nt], ah[mt], bl[nt]);
#pragma unroll
            for (int mt = 0; mt < MT; mt++)
#pragma unroll
                for (int nt = 0; nt < 4; nt++) mma_bf16(acc[mt][nt], al[mt], bh[nt]);
        }
        __syncthreads();
    }

#pragma unroll
    for (int mt = 0; mt < MT; mt++) {
#pragma unroll
        for (int nt = 0; nt < 4; nt++) {
            int c = wcol + nt * 8 + (lane & 3) * 2;
            float b0 = bias[c];
            float b1 = bias[c + 1];
#pragma unroll
            for (int pr = 0; pr < 2; pr++) {
                int rr = row0 + wrow + mt * 16 + (lane >> 2) + pr * 8;
                if (rr < M) {
                    float v0 = acc[mt][nt][2 * pr + 0] + b0;
                    float v1 = acc[mt][nt][2 * pr + 1] + b1;
                    if (ACT) {
                        v0 = v0 > 0.f ? v0 : 0.2f * v0;
                        v1 = v1 > 0.f ? v1 : 0.2f * v1;
                    }
                    *reinterpret_cast<float2*>(C + (size_t)rr * BN + c) =
                        make_float2(v0, v1);
                }
            }
        }
    }
}

// ---------------- per-round pointwise kernels ----------------
__global__ void k_vmsg() {
    int t = blockIdx.x * 256 + threadIdx.x;
    int v = t >> 6;
    int f = t & 63;
    if (v >= NVV) return;
    float sp = 0.f, sn = 0.f, lp = 0.f, ln = 0.f;
    int e0 = g_off[v], e1 = g_off[v + 1];
    for (int i = e0; i < e1; i++) {
        int c = g_ecl[i];
        sp += g_cl[(size_t)c * 64 + f];
        lp += g_cdata[(size_t)c * 128 + f];
    }
    int n0 = g_off[NVV + v], n1 = g_off[NVV + v + 1];
    for (int i = n0; i < n1; i++) {
        int c = g_ecl[i];
        sn += g_cl[(size_t)c * 64 + f];
        ln += g_cdata[(size_t)c * 128 + f];
    }
    float q = g_query[(size_t)v * 64 + f];
    float sigp = 1.f / (1.f + expf(-q));
    float sign = 1.f / (1.f + expf(q));
    g_unit[(size_t)v * 256 + f] = g_vdw[v] * (sn * 0.25f * sign - sp * 0.25f * sigp);
    g_unit[(size_t)v * 256 + 128 + f] = lp * g_dw[v];
    g_unit[(size_t)v * 256 + 192 + f] = ln * g_dw[NVV + v];
}

__global__ void k_pnsum2(const float* __restrict__ x, int ld,
                         const int* __restrict__ goff) {
    int g = blockIdx.x / PNB;
    int p = blockIdx.x % PNB;
    int s = goff[g], e = goff[g + 1];
    int n = e - s;
    int chunk = (n + PNB - 1) / PNB;
    int r0 = s + p * chunk;
    int r1 = min(r0 + chunk, e);
    int f = threadIdx.x & 63;
    int rs = threadIdx.x >> 6;
    float a1 = 0.f, a2 = 0.f;
    for (int r = r0 + rs; r < r1; r += 4) {
        float xv = x[(size_t)r * ld + f];
        a1 += xv;
        a2 += xv * xv;
    }
    __shared__ float sh[4][128];
    sh[rs][f] = a1;
    sh[rs][64 + f] = a2;
    __syncthreads();
    if (rs == 0) {
        g_psum[(g * PNB + p) * 128 + f] =
            sh[0][f] + sh[1][f] + sh[2][f] + sh[3][f];
        g_psum[(g * PNB + p) * 128 + 64 + f] =
            sh[0][64 + f] + sh[1][64 + f] + sh[2][64 + f] + sh[3][64 + f];
    }
}

__global__ void k_pnfin2(const int* __restrict__ goff) {
    int i = blockIdx.x * 256 + threadIdx.x;
    if (i < NGG * 64) {
        int g = i >> 6;
        int f = i & 63;
        float s1 = 0.f, s2 = 0.f;
        for (int p = 0; p < PNB; p++) {
            s1 += g_psum[(g * PNB + p) * 128 + f];
            s2 += g_psum[(g * PNB + p) * 128 + 64 + f];
        }
        float cnt = fmaxf((float)(goff[g + 1] - goff[g]), 1.f);
        float m = s1 / cnt;
        float var = fmaxf(s2 / cnt - m * m, 0.f);
        g_mean[i] = m;
        g_rstd[i] = rsqrtf(var + EPSV);
    }
}

__global__ void k_apply_c(const int* __restrict__ clause_gid) {
    int t = blockIdx.x * 256 + threadIdx.x;
    int r = t >> 6;
    int f = t & 63;
    if (r < NCC) {
        int g = clause_gid[r];
        float y = (g_cdata[(size_t)r * 128 + 64 + f] - g_mean[g * 64 + f]) *
                      g_rstd[g * 64 + f] * 0.25f +
                  0.1f * g_clauses[(size_t)r * 64 + f];
        g_clauses[(size_t)r * 64 + f] = y;
    }
}

__global__ void k_apply_v(const int* __restrict__ var_gid) {
    int t = blockIdx.x * 256 + threadIdx.x;
    int r = t >> 6;
    int f = t & 63;
    if (r < NVV) {
        int g = var_gid[r];
        float y = (g_uout[(size_t)r * 64 + f] - g_mean[g * 64 + f]) *
                      g_rstd[g * 64 + f] * 0.25f +
                  0.1f * g_variables[(size_t)r * 64 + f];
        g_variables[(size_t)r * 64 + f] = y;
        g_unit[(size_t)r * 256 + 64 + f] = y;
    }
}

__global__ void k_out(const float* __restrict__ oh,
                      const float* __restrict__ oW1,
                      const float* __restrict__ ob1,
                      float* __restrict__ out) {
    __shared__ float w[64];
    int tid = threadIdx.x;
    if (tid < 64) w[tid] = oW1[tid];
    __syncthreads();
    int warp = tid >> 5;
    int lane = tid & 31;
    int c = blockIdx.x * 8 + warp;
    if (c >= NCC) return;
    float s = oh[(size_t)c * 64 + lane] * w[lane] +
              oh[(size_t)c * 64 + 32 + lane] * w[32 + lane];
#pragma unroll
    for (int d = 16; d; d >>= 1) s += __shfl_down_sync(0xffffffffu, s, d);
    if (lane == 0) {
        float z = s + ob1[0];
        out[c] = 1.f / (1.f + expf(-z));
        out[NCC + c] = fmaxf(z, 0.f) + log1pf(expf(-fabsf(z)));
    }
}

// ---------------- host driver ----------------
extern "C" void kernel_launch(void* const* d_in, const int* in_sizes, int n_in,
                              void* d_out, int out_size) {
    const int*   lit_idx    = (const int*)d_in[0];
    const int*   var_gid    = (const int*)d_in[2];
    const int*   clause_gid = (const int*)d_in[3];
    const float* noise      = (const float*)d_in[4];
    const float* qW0 = (const float*)d_in[5];
    const float* qb0 = (const float*)d_in[6];
    const float* qW1 = (const float*)d_in[7];
    const float* qb1 = (const float*)d_in[8];
    const float* cW0 = (const float*)d_in[9];
    const float* cb0 = (const float*)d_in[10];
    const float* cW1 = (const float*)d_in[11];
    const float* cb1 = (const float*)d_in[12];
    const float* uW0 = (const float*)d_in[13];
    const float* ub0 = (const float*)d_in[14];
    const float* uW1 = (const float*)d_in[15];
    const float* ub1 = (const float*)d_in[16];
    const float* uW2 = (const float*)d_in[17];
    const float* ub2 = (const float*)d_in[18];
    const float* oW0 = (const float*)d_in[19];
    const float* ob0 = (const float*)d_in[20];
    const float* oW1 = (const float*)d_in[21];
    const float* ob1 = (const float*)d_in[22];
    float* out = (float*)d_out;

    float* p_vars = 0;
    float* p_clauses = 0;
    float* p_unit = 0;
    float* p_cdata = 0;
    float* p_cl = 0;
    float* p_ch = 0;
    float* p_query = 0;
    float* p_uout = 0;
    int* p_goff_v = 0;
    int* p_goff_c = 0;
    __nv_bfloat16* p_whi = 0;
    __nv_bfloat16* p_wlo = 0;
    cudaGetSymbolAddress((void**)&p_vars, g_variables);
    cudaGetSymbolAddress((void**)&p_clauses, g_clauses);
    cudaGetSymbolAddress((void**)&p_unit, g_unit);
    cudaGetSymbolAddress((void**)&p_cdata, g_cdata);
    cudaGetSymbolAddress((void**)&p_cl, g_cl);
    cudaGetSymbolAddress((void**)&p_ch, g_ch);
    cudaGetSymbolAddress((void**)&p_query, g_query);
    cudaGetSymbolAddress((void**)&p_uout, g_uout);
    cudaGetSymbolAddress((void**)&p_goff_v, g_goff_v);
    cudaGetSymbolAddress((void**)&p_goff_c, g_goff_c);
    cudaGetSymbolAddress((void**)&p_whi, g_whi);
    cudaGetSymbolAddress((void**)&p_wlo, g_wlo);

    cudaFuncSetAttribute(k_mlp<3, 1, 64, 2, 0, 64, 0>,
                         cudaFuncAttributeMaxDynamicSharedMemorySize, SM_Q);
    cudaFuncSetAttribute(k_mlp<4, 2, 128, 2, 0, 128, 1>,
                         cudaFuncAttributeMaxDynamicSharedMemorySize, SM_C);
    cudaFuncSetAttribute(k_mlp<4, 2, 128, 2, 0, 128, 0>,
                         cudaFuncAttributeMaxDynamicSharedMemorySize, SM_C);
    cudaFuncSetAttribute(k_mlp<8, 0, 128, 3, 128, 64, 0>,
                         cudaFuncAttributeMaxDynamicSharedMemorySize, SM_U);

    // ---- setup ----
    k_setup_init<<<cdiv(NCC * 64, 256), 256>>>();
    k_countall<<<cdiv(NEE, 256), 256>>>(lit_idx, var_gid, clause_gid);
    k_scan<<<1, 1024>>>();
    k_fill<<<cdiv(NEE, 256), 256>>>(lit_idx);
    k_wsplit_all<<<cdiv(WPOOL, 256), 256>>>(qW0, qW1, cW0, cW1, uW0, uW1, uW2, oW0);

    const int GV = cdiv(NVV, 128);
    const int GC = cdiv(NCC, 128);
    const float* fnull = 0;
    const int* inull = 0;
    const __nv_bfloat16* bnull = 0;

    for (int t = 0; t < RNDS; t++) {
        const float* noise_t = noise + (size_t)t * NVV * 4;
        bool last = (t == RNDS - 1);

        k_mlp<3, 1, 64, 2, 0, 64, 0><<<GV, 256, SM_Q>>>(
            NVV, p_vars, 64, noise_t, inull, fnull, (float*)0,
            p_whi + OQ0, p_wlo + OQ0, qb0,
            p_whi + OQ1, p_wlo + OQ1, qb1,
            bnull, bnull, fnull, p_query);

        if (!last) {
            k_mlp<4, 2, 128, 2, 0, 128, 1><<<GC, 256, SM_C>>>(
                NCC, p_clauses, 64, fnull, lit_idx, p_query, p_cl,
                p_whi + OC0, p_wlo + OC0, cb0,
                p_whi + OC1, p_wlo + OC1, cb1,
                bnull, bnull, fnull, p_cdata);
            k_vmsg<<<cdiv(NVV * 64, 256), 256>>>();
        } else {
            k_mlp<4, 2, 128, 2, 0, 128, 0><<<GC, 256, SM_C>>>(
                NCC, p_clauses, 64, fnull, lit_idx, p_query, (float*)0,
                p_whi + OC0, p_wlo + OC0, cb0,
                p_whi + OC1, p_wlo + OC1, cb1,
                bnull, bnull, fnull, p_cdata);
        }

        k_pnsum2<<<NGG * PNB, 256>>>(p_cdata + 64, 128, p_goff_c);
        k_pnfin2<<<8, 256>>>(p_goff_c);
        k_apply_c<<<cdiv(NCC * 64, 256), 256>>>(clause_gid);

        if (!last) {
            k_mlp<8, 0, 128, 3, 128, 64, 0><<<GV, 256, SM_U>>>(
                NVV, p_unit, 256, fnull, inull, fnull, (float*)0,
                p_whi + OU0, p_wlo + OU0, ub0,
                p_whi + OU1, p_wlo + OU1, ub1,
                p_whi + OU2, p_wlo + OU2, ub2, p_uout);
            k_pnsum2<<<NGG * PNB, 256>>>(p_uout, 64, p_goff_v);
            k_pnfin2<<<8, 256>>>(p_goff_v);
            k_apply_v<<<cdiv(NVV * 64, 256), 256>>>(var_gid);
        }
    }

    k_tcgemm<64, 1><<<GC, 256>>>(NCC, 64, 64, p_clauses, 64,
                                 p_whi + OO0, p_wlo + OO0, ob0, p_ch);
    k_out<<<cdiv(NCC, 8), 256>>>(p_ch, oW1, ob1, out);
}

// round 17
// speedup vs baseline: 1.4014x; 1.1087x over previous
#include <cuda_runtime.h>
#include <cuda_bf16.h>
#include <cstdint>
#include <math.h>

typedef unsigned int u32;

#define NVV 50000
#define NCC 210000
#define NEE 630000
#define NGG 32
#define RNDS 16
#define PNB 16
#define EPSV 1e-6f
#define VMB 12500

// ---------------- scratch (static device globals; no allocation) ----------------
__device__ float g_variables[NVV * 64];
__device__ float g_clauses[NCC * 64];
__device__ float g_unit[NVV * 256];      // [vgrad | variables | vl_pos | vl_neg]
__device__ float g_cdata[NCC * 128];     // clause_data = [varloss_all | prenorm]
__device__ float g_cl[NCC * 64];         // 4*exp(-cv) per clause (for vmsg)
__device__ float g_ch[NCC * 64];         // o-MLP hidden
__device__ float g_query[NVV * 64];
__device__ float g_uout[NVV * 64];

__device__ int   g_cnt[2 * NVV];
__device__ int   g_off[2 * NVV + 1];
__device__ int   g_cur[2 * NVV];
__device__ int   g_ecl[NEE];
__device__ float g_dw[2 * NVV];
__device__ float g_vdw[NVV];
__device__ int   g_gcnt_v[NGG];
__device__ int   g_gcnt_c[NGG];
__device__ int   g_goff_v[NGG + 1];
__device__ int   g_goff_c[NGG + 1];
__device__ float g_psum[NGG * PNB * 128];
__device__ float g_mean[NGG * 64];
__device__ float g_rstd[NGG * 64];

// bf16 hi/lo weight pools (padded K)
#define OQ0 0
#define OQ1 6144
#define OC0 10240
#define OC1 26624
#define OU0 43008
#define OU1 75776
#define OU2 92160
#define OO0 100352
#define WPOOL 104448
__device__ __nv_bfloat16 g_whi[WPOOL];
__device__ __nv_bfloat16 g_wlo[WPOOL];

#define SMEMSZ 110592

static inline int cdiv(int a, int b) { return (a + b - 1) / b; }

// ---------------- setup kernels ----------------
__global__ void k_setup_init() {
    int i = blockIdx.x * 256 + threadIdx.x;
    if (i < NCC * 64) g_clauses[i] = 1.f;
    if (i < NVV * 64) {
        g_variables[i] = 1.f;
        int r = i >> 6;
        int c = i & 63;
        g_unit[r * 256 + 64 + c] = 1.f;
    }
    if (i < 2 * NVV) g_cnt[i] = 0;
    if (i < NGG) {
        g_gcnt_v[i] = 0;
        g_gcnt_c[i] = 0;
    }
}

__global__ void k_countall(const int* __restrict__ lit_idx,
                           const int* __restrict__ var_gid,
                           const int* __restrict__ clause_gid) {
    int i = blockIdx.x * 256 + threadIdx.x;
    if (i < NEE) atomicAdd(&g_cnt[lit_idx[i]], 1);
    if (i < NVV) atomicAdd(&g_gcnt_v[var_gid[i]], 1);
    if (i < NCC) atomicAdd(&g_gcnt_c[clause_gid[i]], 1);
}

__global__ void k_scan() {
    __shared__ int ssum[1024];
    int tid = threadIdx.x;
    const int Ntot = 2 * NVV;
    int chunk = (Ntot + 1023) / 1024;
    int base = tid * chunk;
    int s = 0;
    for (int i = 0; i < chunk; i++) {
        int idx = base + i;
        if (idx < Ntot) s += g_cnt[idx];
    }
    ssum[tid] = s;
    __syncthreads();
    for (int d = 1; d < 1024; d <<= 1) {
        int v = (tid >= d) ? ssum[tid - d] : 0;
        __syncthreads();
        ssum[tid] += v;
        __syncthreads();
    }
    int run = (tid == 0) ? 0 : ssum[tid - 1];
    for (int i = 0; i < chunk; i++) {
        int idx = base + i;
        if (idx < Ntot) {
            g_off[idx] = run;
            g_cur[idx] = run;
            int c = g_cnt[idx];
            g_dw[idx] = rsqrtf(fmaxf((float)c, 1.f));
            run += c;
        }
    }
    if (tid == 1023) g_off[Ntot] = ssum[1023];
    if (tid == 0) {
        int a = 0;
        for (int g = 0; g < NGG; g++) {
            g_goff_v[g] = a;
            a += g_gcnt_v[g];
        }
        g_goff_v[NGG] = a;
        int b = 0;
        for (int g = 0; g < NGG; g++) {
            g_goff_c[g] = b;
            b += g_gcnt_c[g];
        }
        g_goff_c[NGG] = b;
    }
    __syncthreads();
    for (int v = tid; v < NVV; v += 1024)
        g_vdw[v] = 4.f * rsqrtf(fmaxf((float)(g_cnt[v] + g_cnt[NVV + v]), 1.f));
}

__global__ void k_fill(const int* __restrict__ lit_idx) {
    int e = blockIdx.x * 256 + threadIdx.x;
    if (e < NEE) {
        int p = atomicAdd(&g_cur[lit_idx[e]], 1);
        g_ecl[p] = e / 3;   // clause_idx = repeat(arange(NC), 3)
    }
}

__global__ void k_wsplit_all(const float* __restrict__ qW0, const float* __restrict__ qW1,
                             const float* __restrict__ cW0, const float* __restrict__ cW1,
                             const float* __restrict__ uW0, const float* __restrict__ uW1,
                             const float* __restrict__ uW2, const float* __restrict__ oW0) {
    int i = blockIdx.x * 256 + threadIdx.x;
    if (i >= WPOOL) return;
    const float* W;
    int K, N, local;
    if (i < OQ1)      { W = qW0; K = 68;  N = 64;  local = i - OQ0; }
    else if (i < OC0) { W = qW1; K = 64;  N = 64;  local = i - OQ1; }
    else if (i < OC1) { W = cW0; K = 128; N = 128; local = i - OC0; }
    else if (i < OU0) { W = cW1; K = 128; N = 128; local = i - OC1; }
    else if (i < OU1) { W = uW0; K = 256; N = 128; local = i - OU0; }
    else if (i < OU2) { W = uW1; K = 128; N = 128; local = i - OU1; }
    else if (i < OO0) { W = uW2; K = 128; N = 64;  local = i - OU2; }
    else              { W = oW0; K = 64;  N = 64;  local = i - OO0; }
    int k = local / N;
    float v = (k < K) ? W[local] : 0.f;
    __nv_bfloat16 h = __float2bfloat16(v);
    g_whi[i] = h;
    g_wlo[i] = __float2bfloat16(v - __bfloat162float(h));
}

// ---------------- MMA helpers ----------------
__device__ __forceinline__ u32 smem_u32(const void* p) {
    return (u32)__cvta_generic_to_shared(p);
}

__device__ __forceinline__ void ldsm4(u32& r0, u32& r1, u32& r2, u32& r3, u32 a) {
    asm volatile("ldmatrix.sync.aligned.m8n8.x4.shared.b16 {%0,%1,%2,%3}, [%4];"
                 : "=r"(r0), "=r"(r1), "=r"(r2), "=r"(r3) : "r"(a));
}

__device__ __forceinline__ void ldsm4t(u32& r0, u32& r1, u32& r2, u32& r3, u32 a) {
    asm volatile("ldmatrix.sync.aligned.m8n8.x4.trans.shared.b16 {%0,%1,%2,%3}, [%4];"
                 : "=r"(r0), "=r"(r1), "=r"(r2), "=r"(r3) : "r"(a));
}

__device__ __forceinline__ void mma_bf16(float* c, const u32* a, const u32* b) {
    asm volatile(
        "mma.sync.aligned.m16n8k16.row.col.f32.bf16.bf16.f32 "
        "{%0,%1,%2,%3}, {%4,%5,%6,%7}, {%8,%9}, {%0,%1,%2,%3};"
        : "+f"(c[0]), "+f"(c[1]), "+f"(c[2]), "+f"(c[3])
        : "r"(a[0]), "r"(a[1]), "r"(a[2]), "r"(a[3]), "r"(b[0]), "r"(b[1]));
}

__device__ __forceinline__ float softplusf(float x) {
    return fmaxf(x, 0.f) + log1pf(expf(-fabsf(x)));
}

__device__ __forceinline__ void bsplit(float v, __nv_bfloat16& h, __nv_bfloat16& l) {
    h = __float2bfloat16(v);
    l = __float2bfloat16(v - __bfloat162float(h));
}

// W slab load: 32 rows x NW cols of hi/lo into regs
template <int NW>
__device__ __forceinline__ void wload(int s, int tid,
                                      const __nv_bfloat16* __restrict__ Wh,
                                      const __nv_bfloat16* __restrict__ Wl,
                                      uint4* th, uint4* tl) {
    const uint4* wh4 = reinterpret_cast<const uint4*>(Wh + (size_t)s * 32 * NW);
    const uint4* wl4 = reinterpret_cast<const uint4*>(Wl + (size_t)s * 32 * NW);
    const int NW4 = NW / 64;
    for (int i = 0; i < NW4; i++) {
        th[i] = wh4[tid + i * 256];
        tl[i] = wl4[tid + i * 256];
    }
}

// GEMM phase reading A from smem, W streamed global->smem with reg prefetch
template <int NW, int MT>
__device__ __forceinline__ void mlp_phase(const __nv_bfloat16* Hh, const __nv_bfloat16* Hl,
                                          int hstr, int Kdim,
                                          const __nv_bfloat16* __restrict__ Wh,
                                          const __nv_bfloat16* __restrict__ Wl,
                                          __nv_bfloat16* sWh, __nv_bfloat16* sWl,
                                          int tid, float acc[][4][4]) {
    const int lane = tid & 31;
    const int warp = tid >> 5;
    int wm, wn;
    if (NW == 128) { wm = warp & 1; wn = warp >> 1; }
    else           { wm = warp & 3; wn = warp >> 2; }
    const int wrow = wm * 16 * MT;
    const int wcol = wn * 32;
    const int BSTR = NW + 8;
    const int NW4 = NW / 64;

#pragma unroll
    for (int i = 0; i < MT; i++)
#pragma unroll
        for (int j = 0; j < 4; j++)
#pragma unroll
            for (int q = 0; q < 4; q++) acc[i][j][q] = 0.f;

    uint4 th[2], tl[2];
    wload<NW>(0, tid, Wh, Wl, th, tl);
    const int S = Kdim / 32;
    for (int s = 0; s < S; s++) {
#pragma unroll
        for (int i = 0; i < NW4; i++) {
            int f = tid + i * 256;
            int r = f / (NW / 8);
            int n8 = f % (NW / 8);
            *reinterpret_cast<uint4*>(&sWh[r * BSTR + n8 * 8]) = th[i];
            *reinterpret_cast<uint4*>(&sWl[r * BSTR + n8 * 8]) = tl[i];
        }
        __syncthreads();
        if (s + 1 < S) wload<NW>(s + 1, tid, Wh, Wl, th, tl);
#pragma unroll
        for (int ks = 0; ks < 32; ks += 16) {
            int kk = s * 32 + ks;
            u32 ah[MT][4], al[MT][4];
#pragma unroll
            for (int mt = 0; mt < MT; mt++) {
                int r = wrow + mt * 16 + (lane & 15);
                int ko = kk + ((lane >> 4) << 3);
                ldsm4(ah[mt][0], ah[mt][1], ah[mt][2], ah[mt][3],
                      smem_u32(&Hh[r * hstr + ko]));
                ldsm4(al[mt][0], al[mt][1], al[mt][2], al[mt][3],
                      smem_u32(&Hl[r * hstr + ko]));
            }
            u32 bh[4][2], bl[4][2];
#pragma unroll
            for (int half = 0; half < 2; half++) {
                int k = ks + (lane & 15);
                int n = wcol + half * 16 + ((lane >> 4) << 3);
                u32 r0, r1, r2, r3;
                ldsm4t(r0, r1, r2, r3, smem_u32(&sWh[k * BSTR + n]));
                bh[half * 2 + 0][0] = r0;
                bh[half * 2 + 0][1] = r1;
                bh[half * 2 + 1][0] = r2;
                bh[half * 2 + 1][1] = r3;
                ldsm4t(r0, r1, r2, r3, smem_u32(&sWl[k * BSTR + n]));
                bl[half * 2 + 0][0] = r0;
                bl[half * 2 + 0][1] = r1;
                bl[half * 2 + 1][0] = r2;
                bl[half * 2 + 1][1] = r3;
            }
#pragma unroll
            for (int mt = 0; mt < MT; mt++)
#pragma unroll
                for (int nt = 0; nt < 4; nt++) mma_bf16(acc[mt][nt], ah[mt], bh[nt]);
#pragma unroll
            for (int mt = 0; mt < MT; mt++)
#pragma unroll
                for (int nt = 0; nt < 4; nt++) mma_bf16(acc[mt][nt], ah[mt], bl[nt]);
#pragma unroll
            for (int mt = 0; mt < MT; mt++)
#pragma unroll
                for (int nt = 0; nt < 4; nt++) mma_bf16(acc[mt][nt], al[mt], bh[nt]);
        }
        __syncthreads();
    }
}

template <int NW, int MT>
__device__ __forceinline__ void epi_to_smem(float acc[][4][4],
                                            const float* __restrict__ bias,
                                            __nv_bfloat16* Hh, __nv_bfloat16* Hl,
                                            int hstr, int tid) {
    const int lane = tid & 31;
    const int warp = tid >> 5;
    int wm, wn;
    if (NW == 128) { wm = warp & 1; wn = warp >> 1; }
    else           { wm = warp & 3; wn = warp >> 2; }
    const int wrow = wm * 16 * MT;
    const int wcol = wn * 32;
#pragma unroll
    for (int mt = 0; mt < MT; mt++) {
#pragma unroll
        for (int nt = 0; nt < 4; nt++) {
            int c = wcol + nt * 8 + (lane & 3) * 2;
            float b0 = bias[c];
            float b1 = bias[c + 1];
#pragma unroll
            for (int pr = 0; pr < 2; pr++) {
                int r = wrow + mt * 16 + (lane >> 2) + pr * 8;
                float v0 = acc[mt][nt][2 * pr + 0] + b0;
                float v1 = acc[mt][nt][2 * pr + 1] + b1;
                v0 = v0 > 0.f ? v0 : 0.2f * v0;
                v1 = v1 > 0.f ? v1 : 0.2f * v1;
                __nv_bfloat16 h0, l0, h1, l1;
                bsplit(v0, h0, l0);
                bsplit(v1, h1, l1);
                Hh[r * hstr + c] = h0;
                Hh[r * hstr + c + 1] = h1;
                Hl[r * hstr + c] = l0;
                Hl[r * hstr + c + 1] = l1;
            }
        }
    }
}

template <int NW, int MT>
__device__ __forceinline__ void epi_to_global(float acc[][4][4],
                                              const float* __restrict__ bias,
                                              float* __restrict__ OUT, int M,
                                              int row0, int tid) {
    const int lane = tid & 31;
    const int warp = tid >> 5;
    int wm, wn;
    if (NW == 128) { wm = warp & 1; wn = warp >> 1; }
    else           { wm = warp & 3; wn = warp >> 2; }
    const int wrow = wm * 16 * MT;
    const int wcol = wn * 32;
#pragma unroll
    for (int mt = 0; mt < MT; mt++) {
#pragma unroll
        for (int nt = 0; nt < 4; nt++) {
            int c = wcol + nt * 8 + (lane & 3) * 2;
            float b0 = bias[c];
            float b1 = bias[c + 1];
#pragma unroll
            for (int pr = 0; pr < 2; pr++) {
                int rr = row0 + wrow + mt * 16 + (lane >> 2) + pr * 8;
                if (rr < M) {
                    float v0 = acc[mt][nt][2 * pr + 0] + b0;
                    float v1 = acc[mt][nt][2 * pr + 1] + b1;
                    *reinterpret_cast<float2*>(OUT + (size_t)rr * NW + c) =
                        make_float2(v0, v1);
                }
            }
        }
    }
}

// ---------------- fused multi-layer MLP kernel (R6 structure) ----------------
// MODE 0: A = A0[M, lda0]; MODE 1: [vars|noise]; MODE 2: [clauses | 4*exp(-cv)]
template <int K1S, int MODE, int H1, int NL, int H2, int HOUT, int WCL>
__launch_bounds__(256)
__global__ void k_mlp(int M,
                      const float* __restrict__ A0, int lda0,
                      const float* __restrict__ A1,
                      const int* __restrict__ lit,
                      const float* __restrict__ query,
                      float* __restrict__ clout,
                      const __nv_bfloat16* __restrict__ W1h,
                      const __nv_bfloat16* __restrict__ W1l,
                      const float* __restrict__ b1,
                      const __nv_bfloat16* __restrict__ W2h,
                      const __nv_bfloat16* __restrict__ W2l,
                      const float* __restrict__ b2,
                      const __nv_bfloat16* __restrict__ W3h,
                      const __nv_bfloat16* __restrict__ W3l,
                      const float* __restrict__ b3,
                      float* __restrict__ OUT) {
    extern __shared__ char smem[];
    const int ASTR = 40;
    __nv_bfloat16* sAh = (__nv_bfloat16*)smem;
    __nv_bfloat16* sAl = sAh + 128 * ASTR;
    __nv_bfloat16* sWh = sAl + 128 * ASTR;
    __nv_bfloat16* sWl = sWh + 32 * 136;
    __nv_bfloat16* sHh = sWl + 32 * 136;
    __nv_bfloat16* sHl = sHh + 128 * 136;
    int* sLit = (int*)(sHl + 128 * 136);

    const int tid = threadIdx.x;
    const int lane = tid & 31;
    const int warp = tid >> 5;
    const int row0 = blockIdx.x * 128;
    const int HSTR1 = H1 + 8;

    if (MODE == 2) {
        for (int i = tid; i < 128 * 3; i += 256) {
            int r = i / 3;
            int j = i % 3;
            int row = row0 + r;
            sLit[i] = (row < M) ? lit[row * 3 + j] : 0;
        }
    }
    __syncthreads();

    const int MT1 = (H1 == 128) ? 4 : 2;
    int wm1, wn1;
    if (H1 == 128) { wm1 = warp & 1; wn1 = warp >> 1; }
    else           { wm1 = warp & 3; wn1 = warp >> 2; }
    const int wrow1 = wm1 * 16 * MT1;
    const int wcol1 = wn1 * 32;
    const int BSTR1 = H1 + 8;
    const int NW41 = H1 / 64;

    float acc[4][4][4];
#pragma unroll
    for (int i = 0; i < MT1; i++)
#pragma unroll
        for (int j = 0; j < 4; j++)
#pragma unroll
            for (int q = 0; q < 4; q++) acc[i][j][q] = 0.f;

    for (int s = 0; s < K1S; s++) {
        float4 ar[4];
#pragma unroll
        for (int i = 0; i < 4; i++) {
            int f = tid + i * 256;
            int r = f >> 3;
            int c4 = f & 7;
            int col = s * 32 + c4 * 4;
            int row = row0 + r;
            float4 v = make_float4(0.f, 0.f, 0.f, 0.f);
            if (row < M) {
                if (MODE == 0) {
                    v = *reinterpret_cast<const float4*>(A0 + (size_t)row * lda0 + col);
                } else if (MODE == 1) {
                    if (col < 64)
                        v = *reinterpret_cast<const float4*>(A0 + (size_t)row * 64 + col);
                    else if (col == 64)
                        v = *reinterpret_cast<const float4*>(A1 + (size_t)row * 4);
                } else {
                    if (s < 2) {
                        v = *reinterpret_cast<const float4*>(A0 + (size_t)row * 64 + col);
                    } else {
                        int fc = col - 64;
                        float cv0 = 0.f, cv1 = 0.f, cv2 = 0.f, cv3 = 0.f;
#pragma unroll
                        for (int j = 0; j < 3; j++) {
                            int l = sLit[r * 3 + j];
                            int qr = (l < NVV) ? l : (l - NVV);
                            float sg = (l < NVV) ? 1.f : -1.f;
                            float4 qv = *reinterpret_cast<const float4*>(
                                query + (size_t)qr * 64 + fc);
                            cv0 += softplusf(sg * qv.x);
                            cv1 += softplusf(sg * qv.y);
                            cv2 += softplusf(sg * qv.z);
                            cv3 += softplusf(sg * qv.w);
                        }
                        v = make_float4(4.f * expf(-cv0), 4.f * expf(-cv1),
                                        4.f * expf(-cv2), 4.f * expf(-cv3));
                        if (WCL)
                            *reinterpret_cast<float4*>(clout + (size_t)row * 64 + fc) = v;
                    }
                }
            }
            ar[i] = v;
        }
        uint4 th[2], tl[2];
        const uint4* wh4 = reinterpret_cast<const uint4*>(W1h + (size_t)s * 32 * H1);
        const uint4* wl4 = reinterpret_cast<const uint4*>(W1l + (size_t)s * 32 * H1);
#pragma unroll
        for (int i = 0; i < NW41; i++) {
            th[i] = wh4[tid + i * 256];
            tl[i] = wl4[tid + i * 256];
        }
        __syncthreads();
#pragma unroll
        for (int i = 0; i < 4; i++) {
            int f = tid + i * 256;
            int r = f >> 3;
            int c4 = f & 7;
            float4 v = ar[i];
            __nv_bfloat16 h0, l0, h1, l1, h2, l2, h3, l3;
            bsplit(v.x, h0, l0);
            bsplit(v.y, h1, l1);
            bsplit(v.z, h2, l2);
            bsplit(v.w, h3, l3);
            __nv_bfloat16* ph = &sAh[r * ASTR + c4 * 4];
            __nv_bfloat16* pl = &sAl[r * ASTR + c4 * 4];
            ph[0] = h0; ph[1] = h1; ph[2] = h2; ph[3] = h3;
            pl[0] = l0; pl[1] = l1; pl[2] = l2; pl[3] = l3;
        }
#pragma unroll
        for (int i = 0; i < NW41; i++) {
            int f = tid + i * 256;
            int r = f / (H1 / 8);
            int n8 = f % (H1 / 8);
            *reinterpret_cast<uint4*>(&sWh[r * BSTR1 + n8 * 8]) = th[i];
            *reinterpret_cast<uint4*>(&sWl[r * BSTR1 + n8 * 8]) = tl[i];
        }
        __syncthreads();
#pragma unroll
        for (int ks = 0; ks < 32; ks += 16) {
            u32 ah[4][4], al[4][4];
#pragma unroll
            for (int mt = 0; mt < MT1; mt++) {
                int r = wrow1 + mt * 16 + (lane & 15);
                int ko = ks + ((lane >> 4) << 3);
                ldsm4(ah[mt][0], ah[mt][1], ah[mt][2], ah[mt][3],
                      smem_u32(&sAh[r * ASTR + ko]));
                ldsm4(al[mt][0], al[mt][1], al[mt][2], al[mt][3],
                      smem_u32(&sAl[r * ASTR + ko]));
            }
            u32 bh[4][2], bl[4][2];
#pragma unroll
            for (int half = 0; half < 2; half++) {
                int k = ks + (lane & 15);
                int n = wcol1 + half * 16 + ((lane >> 4) << 3);
                u32 r0, r1, r2, r3;
                ldsm4t(r0, r1, r2, r3, smem_u32(&sWh[k * BSTR1 + n]));
                bh[half * 2 + 0][0] = r0;
                bh[half * 2 + 0][1] = r1;
                bh[half * 2 + 1][0] = r2;
                bh[half * 2 + 1][1] = r3;
                ldsm4t(r0, r1, r2, r3, smem_u32(&sWl[k * BSTR1 + n]));
                bl[half * 2 + 0][0] = r0;
                bl[half * 2 + 0][1] = r1;
                bl[half * 2 + 1][0] = r2;
                bl[half * 2 + 1][1] = r3;
            }
#pragma unroll
            for (int mt = 0; mt < MT1; mt++)
#pragma unroll
                for (int nt = 0; nt < 4; nt++) mma_bf16(acc[mt][nt], ah[mt], bh[nt]);
#pragma unroll
            for (int mt = 0; mt < MT1; mt++)
#pragma unroll
                for (int nt = 0; nt < 4; nt++) mma_bf16(acc[mt][nt], ah[mt], bl[nt]);
#pragma unroll
            for (int mt = 0; mt < MT1; mt++)
#pragma unroll
                for (int nt = 0; nt < 4; nt++) mma_bf16(acc[mt][nt], al[mt], bh[nt]);
        }
        __syncthreads();
    }
    epi_to_smem<H1, (H1 == 128) ? 4 : 2>(acc, b1, sHh, sHl, HSTR1, tid);
    __syncthreads();

    if (NL == 2) {
        mlp_phase<HOUT, (HOUT == 128) ? 4 : 2>(sHh, sHl, HSTR1, H1, W2h, W2l,
                                               sWh, sWl, tid, acc);
        epi_to_global<HOUT, (HOUT == 128) ? 4 : 2>(acc, b2, OUT, M, row0, tid);
    } else {
        mlp_phase<H2, (H2 == 128) ? 4 : 2>(sHh, sHl, HSTR1, H1, W2h, W2l,
                                           sWh, sWl, tid, acc);
        epi_to_smem<H2, (H2 == 128) ? 4 : 2>(acc, b2, sHh, sHl, H2 + 8, tid);
        __syncthreads();
        mlp_phase<HOUT, (HOUT == 128) ? 4 : 2>(sHh, sHl, H2 + 8, H2, W3h, W3l,
                                               sWh, sWl, tid, acc);
        epi_to_global<HOUT, (HOUT == 128) ? 4 : 2>(acc, b3, OUT, M, row0, tid);
    }
}

// ---------------- single-layer GEMM (o-MLP hidden only) ----------------
template <int BN>
__device__ __forceinline__ void tc_load(int k0, int tid, int row0, int M, int K0,
                                        const float* __restrict__ A0, int lda0,
                                        const __nv_bfloat16* __restrict__ Whi,
                                        const __nv_bfloat16* __restrict__ Wlo,
                                        float4* ar, uint4* wh, uint4* wl) {
    for (int i = 0; i < 4; i++) {
        int f = tid + i * 256;
        int r = f >> 3;
        int c4 = f & 7;
        int col = k0 + c4 * 4;
        int grow = row0 + r;
        float4 v = make_float4(0.f, 0.f, 0.f, 0.f);
        if (grow < M && col + 4 <= K0)
            v = *reinterpret_cast<const float4*>(A0 + (size_t)grow * lda0 + col);
        ar[i] = v;
    }
    const uint4* wh4 = reinterpret_cast<const uint4*>(Whi + (size_t)k0 * BN);
    const uint4* wl4 = reinterpret_cast<const uint4*>(Wlo + (size_t)k0 * BN);
    const int NW4 = BN / 64;
    for (int i = 0; i < NW4; i++) {
        wh[i] = wh4[tid + i * 256];
        wl[i] = wl4[tid + i * 256];
    }
}

template <int BN, int ACT>
__launch_bounds__(256, 1)
__global__ void k_tcgemm(int M, int K0, int Kpad,
                         const float* __restrict__ A0, int lda0,
                         const __nv_bfloat16* __restrict__ Whi,
                         const __nv_bfloat16* __restrict__ Wlo,
                         const float* __restrict__ bias,
                         float* __restrict__ C) {
    const int ASTR = 40;
    const int BSTR = BN + 8;
    const int WM = (BN == 128) ? 64 : 32;
    const int MT = WM / 16;
    const int NW4 = BN / 64;

    __shared__ __nv_bfloat16 Ash[128 * ASTR];
    __shared__ __nv_bfloat16 Asl[128 * ASTR];
    __shared__ __nv_bfloat16 Bsh[32 * (BN + 8)];
    __shared__ __nv_bfloat16 Bsl[32 * (BN + 8)];

    const int tid = threadIdx.x;
    const int lane = tid & 31;
    const int warp = tid >> 5;
    const int row0 = blockIdx.x * 128;
    int wm, wn;
    if (BN == 128) { wm = warp & 1; wn = warp >> 1; }
    else { wm = warp & 3; wn = warp >> 2; }
    const int wrow = wm * WM;
    const int wcol = wn * 32;

    float acc[MT][4][4];
#pragma unroll
    for (int i = 0; i < MT; i++)
#pragma unroll
        for (int j = 0; j < 4; j++)
#pragma unroll
            for (int q = 0; q < 4; q++) acc[i][j][q] = 0.f;

    const int S = Kpad / 32;
    float4 ar[4];
    uint4 wh[2], wl[2];
    tc_load<BN>(0, tid, row0, M, K0, A0, lda0, Whi, Wlo, ar, wh, wl);

    for (int s = 0; s < S; s++) {
#pragma unroll
        for (int i = 0; i < 4; i++) {
            int f = tid + i * 256;
            int r = f >> 3;
            int c4 = f & 7;
            float4 v = ar[i];
            __nv_bfloat16 h0, l0, h1, l1, h2, l2, h3, l3;
            bsplit(v.x, h0, l0);
            bsplit(v.y, h1, l1);
            bsplit(v.z, h2, l2);
            bsplit(v.w, h3, l3);
            __nv_bfloat16* ph = &Ash[r * ASTR + c4 * 4];
            __nv_bfloat16* pl = &Asl[r * ASTR + c4 * 4];
            ph[0] = h0; ph[1] = h1; ph[2] = h2; ph[3] = h3;
            pl[0] = l0; pl[1] = l1; pl[2] = l2; pl[3] = l3;
        }
#pragma unroll
        for (int i = 0; i < NW4; i++) {
            int f = tid + i * 256;
            int r = f / (BN / 8);
            int n8 = f % (BN / 8);
            *reinterpret_cast<uint4*>(&Bsh[r * BSTR + n8 * 8]) = wh[i];
            *reinterpret_cast<uint4*>(&Bsl[r * BSTR + n8 * 8]) = wl[i];
        }
        __syncthreads();
        if (s + 1 < S)
            tc_load<BN>((s + 1) * 32, tid, row0, M, K0, A0, lda0, Whi, Wlo, ar, wh, wl);

#pragma unroll
        for (int ks = 0; ks < 32; ks += 16) {
            u32 ah[MT][4], al[MT][4];
#pragma unroll
            for (int mt = 0; mt < MT; mt++) {
                int r = wrow + mt * 16 + (lane & 15);
                int kk = ks + ((lane >> 4) << 3);
                ldsm4(ah[mt][0], ah[mt][1], ah[mt][2], ah[mt][3],
                      smem_u32(&Ash[r * ASTR + kk]));
                ldsm4(al[mt][0], al[mt][1], al[mt][2], al[mt][3],
                      smem_u32(&Asl[r * ASTR + kk]));
            }
            u32 bh[4][2], bl[4][2];
#pragma unroll
            for (int half = 0; half < 2; half++) {
                int k = ks + (lane & 15);
                int n = wcol + half * 16 + ((lane >> 4) << 3);
                u32 r0, r1, r2, r3;
                ldsm4t(r0, r1, r2, r3, smem_u32(&Bsh[k * BSTR + n]));
                bh[half * 2 + 0][0] = r0;
                bh[half * 2 + 0][1] = r1;
                bh[half * 2 + 1][0] = r2;
                bh[half * 2 + 1][1] = r3;
                ldsm4t(r0, r1, r2, r3, smem_u32(&Bsl[k * BSTR + n]));
                bl[half * 2 + 0][0] = r0;
                bl[half * 2 + 0][1] = r1;
                bl[half * 2 + 1][0] = r2;
                bl[half * 2 + 1][1] = r3;
            }
#pragma unroll
            for (int mt = 0; mt < MT; mt++)
#pragma unroll
                for (int nt = 0; nt < 4; nt++) mma_bf16(acc[mt][nt], ah[mt], bh[nt]);
#pragma unroll
            for (int mt = 0; mt < MT; mt++)
#pragma unroll
                for (int nt = 0; nt < 4; nt++) mma_bf16(acc[mt][nt], ah[mt], bl[nt]);
#pragma unroll
            for (int mt = 0; mt < MT; mt++)
#pragma unroll
                for (int nt = 0; nt < 4; nt++) mma_bf16(acc[mt][nt], al[mt], bh[nt]);
        }
        __syncthreads();
    }

#pragma unroll
    for (int mt = 0; mt < MT; mt++) {
#pragma unroll
        for (int nt = 0; nt < 4; nt++) {
            int c = wcol + nt * 8 + (lane & 3) * 2;
            float b0 = bias[c];
            float b1 = bias[c + 1];
#pragma unroll
            for (int pr = 0; pr < 2; pr++) {
                int rr = row0 + wrow + mt * 16 + (lane >> 2) + pr * 8;
                if (rr < M) {
                    float v0 = acc[mt][nt][2 * pr + 0] + b0;
                    float v1 = acc[mt][nt][2 * pr + 1] + b1;
                    if (ACT) {
                        v0 = v0 > 0.f ? v0 : 0.2f * v0;
                        v1 = v1 > 0.f ? v1 : 0.2f * v1;
                    }
                    *reinterpret_cast<float2*>(C + (size_t)rr * BN + c) =
                        make_float2(v0, v1);
                }
            }
        }
    }
}

// ---------------- per-round fused kernels ----------------
// vmsg + clause pnorm moments merged (independent outputs; bodies verified R8)
__global__ void k_vmsg_pns(const int* __restrict__ goffc) {
    __shared__ float sh[4][128];
    if (blockIdx.x < VMB) {
        int t = blockIdx.x * 256 + threadIdx.x;
        int v = t >> 6;
        int f = t & 63;
        if (v >= NVV) return;
        float sp = 0.f, sn = 0.f, lp = 0.f, ln = 0.f;
        int e0 = g_off[v], e1 = g_off[v + 1];
        for (int i = e0; i < e1; i++) {
            int c = g_ecl[i];
            sp += g_cl[(size_t)c * 64 + f];
            lp += g_cdata[(size_t)c * 128 + f];
        }
        int n0 = g_off[NVV + v], n1 = g_off[NVV + v + 1];
        for (int i = n0; i < n1; i++) {
            int c = g_ecl[i];
            sn += g_cl[(size_t)c * 64 + f];
            ln += g_cdata[(size_t)c * 128 + f];
        }
        float q = g_query[(size_t)v * 64 + f];
        float sigp = 1.f / (1.f + expf(-q));
        float sign = 1.f / (1.f + expf(q));
        g_unit[(size_t)v * 256 + f] = g_vdw[v] * (sn * 0.25f * sign - sp * 0.25f * sigp);
        g_unit[(size_t)v * 256 + 128 + f] = lp * g_dw[v];
        g_unit[(size_t)v * 256 + 192 + f] = ln * g_dw[NVV + v];
    } else {
        int b = blockIdx.x - VMB;
        int g = b / PNB;
        int p = b % PNB;
        int s = goffc[g], e = goffc[g + 1];
        int n = e - s;
        int chunk = (n + PNB - 1) / PNB;
        int r0 = s + p * chunk;
        int r1 = min(r0 + chunk, e);
        int f = threadIdx.x & 63;
        int rs = threadIdx.x >> 6;
        float a1 = 0.f, a2 = 0.f;
        for (int r = r0 + rs; r < r1; r += 4) {
            float xv = g_cdata[(size_t)r * 128 + 64 + f];
            a1 += xv;
            a2 += xv * xv;
        }
        sh[rs][f] = a1;
        sh[rs][64 + f] = a2;
        __syncthreads();
        if (rs == 0) {
            g_psum[(g * PNB + p) * 128 + f] = sh[0][f] + sh[1][f] + sh[2][f] + sh[3][f];
            g_psum[(g * PNB + p) * 128 + 64 + f] =
                sh[0][64 + f] + sh[1][64 + f] + sh[2][64 + f] + sh[3][64 + f];
        }
    }
}

__global__ void k_pnsum2(const float* __restrict__ x, int ld,
                         const int* __restrict__ goff) {
    int g = blockIdx.x / PNB;
    int p = blockIdx.x % PNB;
    int s = goff[g], e = goff[g + 1];
    int n = e - s;
    int chunk = (n + PNB - 1) / PNB;
    int r0 = s + p * chunk;
    int r1 = min(r0 + chunk, e);
    int f = threadIdx.x & 63;
    int rs = threadIdx.x >> 6;
    float a1 = 0.f, a2 = 0.f;
    for (int r = r0 + rs; r < r1; r += 4) {
        float xv = x[(size_t)r * ld + f];
        a1 += xv;
        a2 += xv * xv;
    }
    __shared__ float sh[4][128];
    sh[rs][f] = a1;
    sh[rs][64 + f] = a2;
    __syncthreads();
    if (rs == 0) {
        g_psum[(g * PNB + p) * 128 + f] =
            sh[0][f] + sh[1][f] + sh[2][f] + sh[3][f];
        g_psum[(g * PNB + p) * 128 + 64 + f] =
            sh[0][64 + f] + sh[1][64 + f] + sh[2][64 + f] + sh[3][64 + f];
    }
}

__global__ void k_pnfin2(const int* __restrict__ goff) {
    int i = blockIdx.x * 256 + threadIdx.x;
    if (i < NGG * 64) {
        int g = i >> 6;
        int f = i & 63;
        float s1 = 0.f, s2 = 0.f;
        for (int p = 0; p < PNB; p++) {
            s1 += g_psum[(g * PNB + p) * 128 + f];
            s2 += g_psum[(g * PNB + p) * 128 + 64 + f];
        }
        float cnt = fmaxf((float)(goff[g + 1] - goff[g]), 1.f);
        float m = s1 / cnt;
        float var = fmaxf(s2 / cnt - m * m, 0.f);
        g_mean[i] = m;
        g_rstd[i] = rsqrtf(var + EPSV);
    }
}

// float4-vectorized applies (4 features / thread)
__global__ void k_apply_c(const int* __restrict__ clause_gid) {
    int t = blockIdx.x * 256 + threadIdx.x;
    int r = t >> 4;
    int c4 = (t & 15) * 4;
    if (r < NCC) {
        int g = clause_gid[r];
        float4 cd = *reinterpret_cast<const float4*>(&g_cdata[(size_t)r * 128 + 64 + c4]);
        float4 m = *reinterpret_cast<const float4*>(&g_mean[g * 64 + c4]);
        float4 rs = *reinterpret_cast<const float4*>(&g_rstd[g * 64 + c4]);
        float4 co = *reinterpret_cast<const float4*>(&g_clauses[(size_t)r * 64 + c4]);
        float4 y;
        y.x = (cd.x - m.x) * rs.x * 0.25f + 0.1f * co.x;
        y.y = (cd.y - m.y) * rs.y * 0.25f + 0.1f * co.y;
        y.z = (cd.z - m.z) * rs.z * 0.25f + 0.1f * co.z;
        y.w = (cd.w - m.w) * rs.w * 0.25f + 0.1f * co.w;
        *reinterpret_cast<float4*>(&g_clauses[(size_t)r * 64 + c4]) = y;
    }
}

__global__ void k_apply_v(const int* __restrict__ var_gid) {
    int t = blockIdx.x * 256 + threadIdx.x;
    int r = t >> 4;
    int c4 = (t & 15) * 4;
    if (r < NVV) {
        int g = var_gid[r];
        float4 uo = *reinterpret_cast<const float4*>(&g_uout[(size_t)r * 64 + c4]);
        float4 m = *reinterpret_cast<const float4*>(&g_mean[g * 64 + c4]);
        float4 rs = *reinterpret_cast<const float4*>(&g_rstd[g * 64 + c4]);
        float4 vo = *reinterpret_cast<const float4*>(&g_variables[(size_t)r * 64 + c4]);
        float4 y;
        y.x = (uo.x - m.x) * rs.x * 0.25f + 0.1f * vo.x;
        y.y = (uo.y - m.y) * rs.y * 0.25f + 0.1f * vo.y;
        y.z = (uo.z - m.z) * rs.z * 0.25f + 0.1f * vo.z;
        y.w = (uo.w - m.w) * rs.w * 0.25f + 0.1f * vo.w;
        *reinterpret_cast<float4*>(&g_variables[(size_t)r * 64 + c4]) = y;
        *reinterpret_cast<float4*>(&g_unit[(size_t)r * 256 + 64 + c4]) = y;
    }
}

__global__ void k_out(const float* __restrict__ oh,
                      const float* __restrict__ oW1,
                      const float* __restrict__ ob1,
                      float* __restrict__ out) {
    __shared__ float w[64];
    int tid = threadIdx.x;
    if (tid < 64) w[tid] = oW1[tid];
    __syncthreads();
    int warp = tid >> 5;
    int lane = tid & 31;
    int c = blockIdx.x * 8 + warp;
    if (c >= NCC) return;
    float s = oh[(size_t)c * 64 + lane] * w[lane] +
              oh[(size_t)c * 64 + 32 + lane] * w[32 + lane];
#pragma unroll
    for (int d = 16; d; d >>= 1) s += __shfl_down_sync(0xffffffffu, s, d);
    if (lane == 0) {
        float z = s + ob1[0];
        out[c] = 1.f / (1.f + expf(-z));
        out[NCC + c] = fmaxf(z, 0.f) + log1pf(expf(-fabsf(z)));
    }
}

// ---------------- host driver ----------------
extern "C" void kernel_launch(void* const* d_in, const int* in_sizes, int n_in,
                              void* d_out, int out_size) {
    const int*   lit_idx    = (const int*)d_in[0];
    const int*   var_gid    = (const int*)d_in[2];
    const int*   clause_gid = (const int*)d_in[3];
    const float* noise      = (const float*)d_in[4];
    const float* qW0 = (const float*)d_in[5];
    const float* qb0 = (const float*)d_in[6];
    const float* qW1 = (const float*)d_in[7];
    const float* qb1 = (const float*)d_in[8];
    const float* cW0 = (const float*)d_in[9];
    const float* cb0 = (const float*)d_in[10];
    const float* cW1 = (const float*)d_in[11];
    const float* cb1 = (const float*)d_in[12];
    const float* uW0 = (const float*)d_in[13];
    const float* ub0 = (const float*)d_in[14];
    const float* uW1 = (const float*)d_in[15];
    const float* ub1 = (const float*)d_in[16];
    const float* uW2 = (const float*)d_in[17];
    const float* ub2 = (const float*)d_in[18];
    const float* oW0 = (const float*)d_in[19];
    const float* ob0 = (const float*)d_in[20];
    const float* oW1 = (const float*)d_in[21];
    const float* ob1 = (const float*)d_in[22];
    float* out = (float*)d_out;

    float* p_vars = 0;
    float* p_clauses = 0;
    float* p_unit = 0;
    float* p_cdata = 0;
    float* p_cl = 0;
    float* p_ch = 0;
    float* p_query = 0;
    float* p_uout = 0;
    int* p_goff_v = 0;
    int* p_goff_c = 0;
    __nv_bfloat16* p_whi = 0;
    __nv_bfloat16* p_wlo = 0;
    cudaGetSymbolAddress((void**)&p_vars, g_variables);
    cudaGetSymbolAddress((void**)&p_clauses, g_clauses);
    cudaGetSymbolAddress((void**)&p_unit, g_unit);
    cudaGetSymbolAddress((void**)&p_cdata, g_cdata);
    cudaGetSymbolAddress((void**)&p_cl, g_cl);
    cudaGetSymbolAddress((void**)&p_ch, g_ch);
    cudaGetSymbolAddress((void**)&p_query, g_query);
    cudaGetSymbolAddress((void**)&p_uout, g_uout);
    cudaGetSymbolAddress((void**)&p_goff_v, g_goff_v);
    cudaGetSymbolAddress((void**)&p_goff_c, g_goff_c);
    cudaGetSymbolAddress((void**)&p_whi, g_whi);
    cudaGetSymbolAddress((void**)&p_wlo, g_wlo);

    cudaFuncSetAttribute(k_mlp<3, 1, 64, 2, 0, 64, 0>,
                         cudaFuncAttributeMaxDynamicSharedMemorySize, SMEMSZ);
    cudaFuncSetAttribute(k_mlp<4, 2, 128, 2, 0, 128, 1>,
                         cudaFuncAttributeMaxDynamicSharedMemorySize, SMEMSZ);
    cudaFuncSetAttribute(k_mlp<4, 2, 128, 2, 0, 128, 0>,
                         cudaFuncAttributeMaxDynamicSharedMemorySize, SMEMSZ);
    cudaFuncSetAttribute(k_mlp<8, 0, 128, 3, 128, 64, 0>,
                         cudaFuncAttributeMaxDynamicSharedMemorySize, SMEMSZ);

    // ---- setup ----
    k_setup_init<<<cdiv(NCC * 64, 256), 256>>>();
    k_countall<<<cdiv(NEE, 256), 256>>>(lit_idx, var_gid, clause_gid);
    k_scan<<<1, 1024>>>();
    k_fill<<<cdiv(NEE, 256), 256>>>(lit_idx);
    k_wsplit_all<<<cdiv(WPOOL, 256), 256>>>(qW0, qW1, cW0, cW1, uW0, uW1, uW2, oW0);

    const int GV = cdiv(NVV, 128);
    const int GC = cdiv(NCC, 128);
    const float* fnull = 0;
    const int* inull = 0;
    const __nv_bfloat16* bnull = 0;

    for (int t = 0; t < RNDS; t++) {
        const float* noise_t = noise + (size_t)t * NVV * 4;
        bool last = (t == RNDS - 1);

        // q-MLP
        k_mlp<3, 1, 64, 2, 0, 64, 0><<<GV, 256, SMEMSZ>>>(
            NVV, p_vars, 64, noise_t, inull, fnull, (float*)0,
            p_whi + OQ0, p_wlo + OQ0, qb0,
            p_whi + OQ1, p_wlo + OQ1, qb1,
            bnull, bnull, fnull, p_query);

        // c-MLP
        if (!last) {
            k_mlp<4, 2, 128, 2, 0, 128, 1><<<GC, 256, SMEMSZ>>>(
                NCC, p_clauses, 64, fnull, lit_idx, p_query, p_cl,
                p_whi + OC0, p_wlo + OC0, cb0,
                p_whi + OC1, p_wlo + OC1, cb1,
                bnull, bnull, fnull, p_cdata);
            // merged: vgrad/vloss + clause pnorm moments
            k_vmsg_pns<<<VMB + NGG * PNB, 256>>>(p_goff_c);
        } else {
            k_mlp<4, 2, 128, 2, 0, 128, 0><<<GC, 256, SMEMSZ>>>(
                NCC, p_clauses, 64, fnull, lit_idx, p_query, (float*)0,
                p_whi + OC0, p_wlo + OC0, cb0,
                p_whi + OC1, p_wlo + OC1, cb1,
                bnull, bnull, fnull, p_cdata);
            k_pnsum2<<<NGG * PNB, 256>>>(p_cdata + 64, 128, p_goff_c);
        }

        k_pnfin2<<<8, 256>>>(p_goff_c);
        k_apply_c<<<cdiv(NCC * 16, 256), 256>>>(clause_gid);

        if (!last) {
            // u-MLP
            k_mlp<8, 0, 128, 3, 128, 64, 0><<<GV, 256, SMEMSZ>>>(
                NVV, p_unit, 256, fnull, inull, fnull, (float*)0,
                p_whi + OU0, p_wlo + OU0, ub0,
                p_whi + OU1, p_wlo + OU1, ub1,
                p_whi + OU2, p_wlo + OU2, ub2, p_uout);
            k_pnsum2<<<NGG * PNB, 256>>>(p_uout, 64, p_goff_v);
            k_pnfin2<<<8, 256>>>(p_goff_v);
            k_apply_v<<<cdiv(NVV * 16, 256), 256>>>(var_gid);
        }
    }

    // output head
    k_tcgemm<64, 1><<<GC, 256>>>(NCC, 64, 64, p_clauses, 64,
                                 p_whi + OO0, p_wlo + OO0, ob0, p_ch);
    k_out<<<cdiv(NCC, 8), 256>>>(p_ch, oW1, ob1, out);
}